// round 9
// baseline (speedup 1.0000x reference)
#include <cuda_runtime.h>
#include <cuda_fp16.h>
#include <cstdint>
#include <cstddef>

// ---------------- static problem config ----------------
#define IMG    56
#define WIN    7
#define SHIFTS 3
#define CDIM   256
#define NHEAD  8
#define DHEAD  32
#define SWIN   49
#define NWIN   64
#define NMLP   1024
#define BATCH  32
#define NTOK   (BATCH*IMG*IMG)           // 100352
#define QSCALE 0.17677669529663689f

// ---------------- scratch (device globals) ----------------
__device__ __half g_xnh [(size_t)NTOK * CDIM];     // LN1 out fp16
__device__ __half g_oh  [(size_t)NTOK * CDIM];     // attn out fp16
__device__ __half g_xn2h[(size_t)NTOK * CDIM];     // LN2 out fp16
__device__ __half g_hh  [(size_t)NTOK * NMLP];     // gelu out fp16
__device__ float  g_qkv [(size_t)NTOK * 3 * CDIM]; // qkv fp32
__device__ float  g_x1  [(size_t)NTOK * CDIM];     // x + attn
__device__ __half g_wq  [(size_t)(3*CDIM) * CDIM]; // weights [N,K] fp16
__device__ __half g_wp  [(size_t)CDIM * CDIM];
__device__ __half g_w1h [(size_t)NMLP * CDIM];
__device__ __half g_w2h [(size_t)CDIM * NMLP];

// ---------------- helpers ----------------
__device__ __forceinline__ float gelu_exact(float v) {
    return 0.5f * v * (1.0f + erff(v * 0.70710678118654752f));
}
__device__ __forceinline__ uint32_t smem_u32(const void* p) {
    uint32_t a;
    asm("{ .reg .u64 t; cvta.to.shared.u64 t, %1; cvt.u32.u64 %0, t; }"
        : "=r"(a) : "l"(p));
    return a;
}
__device__ __forceinline__ void ldsm4(uint32_t* r, uint32_t addr) {
    asm volatile("ldmatrix.sync.aligned.m8n8.x4.shared.b16 {%0,%1,%2,%3}, [%4];"
        : "=r"(r[0]), "=r"(r[1]), "=r"(r[2]), "=r"(r[3]) : "r"(addr));
}
__device__ __forceinline__ void mma16816(float* c, const uint32_t* a,
                                         uint32_t b0, uint32_t b1) {
    asm volatile("mma.sync.aligned.m16n8k16.row.col.f32.f16.f16.f32 "
        "{%0,%1,%2,%3}, {%4,%5,%6,%7}, {%8,%9}, {%0,%1,%2,%3};"
        : "+f"(c[0]), "+f"(c[1]), "+f"(c[2]), "+f"(c[3])
        : "r"(a[0]), "r"(a[1]), "r"(a[2]), "r"(a[3]), "r"(b0), "r"(b1));
}
__device__ __forceinline__ void cpa16(uint32_t s, const void* g) {
    asm volatile("cp.async.cg.shared.global [%0], [%1], 16;" :: "r"(s), "l"(g));
}
#define CP_COMMIT() asm volatile("cp.async.commit_group;" ::: "memory")
#define CP_WAIT1()  asm volatile("cp.async.wait_group 1;" ::: "memory")
#define CP_WAIT0()  asm volatile("cp.async.wait_group 0;" ::: "memory")

// ---------------- weight prep: W [K,N] fp32 -> Wh [N,K] fp16 ----------------
__global__ void wprep_t(const float* __restrict__ W, __half* __restrict__ Wh,
                        int K, int N)
{
    int idx = blockIdx.x * 256 + threadIdx.x;
    if (idx >= K * N) return;
    int k = idx / N, n = idx - k * N;
    Wh[(size_t)n * K + k] = __float2half_rn(W[idx]);
}

// ---------------- LayerNorm -> fp16: one warp per token ----------------
__global__ __launch_bounds__(256) void ln_h_kernel(
    const float* __restrict__ x,
    const float* __restrict__ gamma,
    const float* __restrict__ beta,
    __half* __restrict__ outh)   // [NTOK, 256] fp16
{
    int lane = threadIdx.x & 31;
    int warp = threadIdx.x >> 5;
    int tok  = blockIdx.x * 8 + warp;

    const float4* px = (const float4*)(x + (size_t)tok * CDIM);
    float4 v0 = px[lane];
    float4 v1 = px[lane + 32];

    float s  = v0.x + v0.y + v0.z + v0.w + v1.x + v1.y + v1.z + v1.w;
    float ss = v0.x*v0.x + v0.y*v0.y + v0.z*v0.z + v0.w*v0.w
             + v1.x*v1.x + v1.y*v1.y + v1.z*v1.z + v1.w*v1.w;
    #pragma unroll
    for (int o = 16; o; o >>= 1) {
        s  += __shfl_xor_sync(0xffffffffu, s,  o);
        ss += __shfl_xor_sync(0xffffffffu, ss, o);
    }
    float mu  = s * (1.0f / 256.0f);
    float var = ss * (1.0f / 256.0f) - mu * mu;
    float rs  = rsqrtf(var + 1e-5f);

    const float4* pg = (const float4*)gamma;
    const float4* pb = (const float4*)beta;
    float4 g0 = pg[lane], g1 = pg[lane + 32];
    float4 b0 = pb[lane], b1 = pb[lane + 32];

    __half2 o0, o1, o2, o3;
    o0.x = __float2half_rn((v0.x - mu) * rs * g0.x + b0.x);
    o0.y = __float2half_rn((v0.y - mu) * rs * g0.y + b0.y);
    o1.x = __float2half_rn((v0.z - mu) * rs * g0.z + b0.z);
    o1.y = __float2half_rn((v0.w - mu) * rs * g0.w + b0.w);
    o2.x = __float2half_rn((v1.x - mu) * rs * g1.x + b1.x);
    o2.y = __float2half_rn((v1.y - mu) * rs * g1.y + b1.y);
    o3.x = __float2half_rn((v1.z - mu) * rs * g1.z + b1.z);
    o3.y = __float2half_rn((v1.w - mu) * rs * g1.w + b1.w);

    __half* base = outh + (size_t)tok * CDIM;
    *(__half2*)(base + lane * 4)       = o0;
    *(__half2*)(base + lane * 4 + 2)   = o1;
    *(__half2*)(base + 128 + lane * 4)     = o2;
    *(__half2*)(base + 128 + lane * 4 + 2) = o3;
}

// ---------------- HMMA GEMM: 128x128 tile, BK=64, plain fp16 ----------------
// A [M, K] fp16, Bw [N, K] fp16.
// EPI 0: outh = fp16(gelu(acc + bias)); EPI 1: outf = res + acc + bias; EPI 2: outf = acc + bias
#define HG_SMEM 65536

template<int EPI>
__global__ __launch_bounds__(256, 2) void hgemm1(
    const __half* __restrict__ A,
    const __half* __restrict__ Bw,
    const float* __restrict__ bias,
    const float* __restrict__ res,
    float* __restrict__ outf,
    __half* __restrict__ outh,
    int M, int N, int K)
{
    extern __shared__ char smem[];
    const uint32_t sAb = smem_u32(smem);            // 2 x 16KB
    const uint32_t sBb = sAb + 32768;               // 2 x 16KB

    const int tid  = threadIdx.x;
    const int lane = tid & 31;
    const int wid  = tid >> 5;
    const int wm   = wid >> 1;       // 0..3
    const int wn   = wid & 1;        // 0..1
    const int row0 = blockIdx.y * 128;
    const int col0 = blockIdx.x * 128;
    const int nch  = K / 64;

    float acc[2][8][4];
    #pragma unroll
    for (int a = 0; a < 2; a++)
        #pragma unroll
        for (int b = 0; b < 8; b++)
            #pragma unroll
            for (int c = 0; c < 4; c++) acc[a][b][c] = 0.f;

    auto issue = [&](int g) {
        uint32_t sa = sAb + (g & 1) * 16384;
        uint32_t sb = sBb + (g & 1) * 16384;
        #pragma unroll
        for (int i = 0; i < 4; i++) {
            int id = tid + i * 256;
            int r = id >> 3, kg = id & 7;
            int sg = kg ^ (r & 7);
            uint32_t so = (uint32_t)(r * 128 + sg * 16);
            cpa16(sa + so, A  + (size_t)(row0 + r) * K + g * 64 + kg * 8);
            cpa16(sb + so, Bw + (size_t)(col0 + r) * K + g * 64 + kg * 8);
        }
        CP_COMMIT();
    };

    issue(0);
    for (int g = 0; g < nch; g++) {
        if (g + 1 < nch) { issue(g + 1); CP_WAIT1(); }
        else             { CP_WAIT0(); }
        __syncthreads();

        const uint32_t aB = sAb + (g & 1) * 16384;
        const uint32_t bB = sBb + (g & 1) * 16384;
        #pragma unroll
        for (int kt = 0; kt < 4; kt++) {
            uint32_t a[2][4], b[4][4];
            const int kg = kt * 2 + (lane >> 4);
            #pragma unroll
            for (int mt = 0; mt < 2; mt++) {
                int r  = wm * 32 + mt * 16 + (lane & 15);
                int sg = kg ^ (r & 7);
                ldsm4(a[mt], aB + (uint32_t)(r * 128 + sg * 16));
            }
            #pragma unroll
            for (int nb = 0; nb < 4; nb++) {
                int r  = wn * 64 + nb * 16 + (lane & 15);
                int sg = kg ^ (r & 7);
                ldsm4(b[nb], bB + (uint32_t)(r * 128 + sg * 16));
            }
            #pragma unroll
            for (int mt = 0; mt < 2; mt++)
                #pragma unroll
                for (int nb = 0; nb < 4; nb++) {
                    mma16816(acc[mt][2 * nb],     a[mt], b[nb][0], b[nb][2]);
                    mma16816(acc[mt][2 * nb + 1], a[mt], b[nb][1], b[nb][3]);
                }
        }
        __syncthreads();
    }

    // epilogue
    const int g4 = lane >> 2, q = lane & 3;
    #pragma unroll
    for (int mt = 0; mt < 2; mt++) {
        #pragma unroll
        for (int half = 0; half < 2; half++) {
            int row = row0 + wm * 32 + mt * 16 + g4 + half * 8;
            #pragma unroll
            for (int nt = 0; nt < 8; nt++) {
                int col = col0 + wn * 64 + nt * 8 + q * 2;
                float v0 = acc[mt][nt][half * 2 + 0] + bias[col];
                float v1 = acc[mt][nt][half * 2 + 1] + bias[col + 1];
                if (EPI == 2) {
                    *(float2*)(outf + (size_t)row * N + col) = make_float2(v0, v1);
                } else if (EPI == 1) {
                    const float2 rv = *(const float2*)(res + (size_t)row * N + col);
                    *(float2*)(outf + (size_t)row * N + col) =
                        make_float2(v0 + rv.x, v1 + rv.y);
                } else {
                    __half2 hp;
                    hp.x = __float2half_rn(gelu_exact(v0));
                    hp.y = __float2half_rn(gelu_exact(v1));
                    *(__half2*)(outh + (size_t)row * N + col) = hp;
                }
            }
        }
    }
}

// ---------------- attention: one CTA per window, one warp per head ----------------
#define KPAD 36
#define VPAD 33
#define SM_KH   0
#define SM_VH   (NHEAD*SWIN*KPAD)
#define SM_AINT (SM_VH + NHEAD*SWIN*VPAD)
#define ATT_SMEM ((SM_AINT + 2*SWIN) * 4)

__global__ __launch_bounds__(256) void attn_kernel(
    const float* __restrict__ qkv,    // [NTOK, 768] (q|k|v)
    const float* __restrict__ btab,   // [169, 8]
    __half* __restrict__ o_h)         // [NTOK, 256] fp16
{
    extern __shared__ float sm[];
    float* kh  = sm + SM_KH;
    float* vh  = sm + SM_VH;
    int* tsrc  = (int*)(sm + SM_AINT);
    int* regid = tsrc + SWIN;

    const int tid  = threadIdx.x;
    const int lane = tid & 31;
    const int h    = tid >> 5;

    const int win = blockIdx.x;
    const int b   = win >> 6;
    const int wq  = win & 63;
    const int wy  = wq >> 3;
    const int wx  = wq & 7;

    if (tid < SWIN) {
        int i = tid / 7, j = tid - i * 7;
        int y  = wy * 7 + i;
        int xx = wx * 7 + j;
        int y0 = y  + SHIFTS; if (y0 >= IMG) y0 -= IMG;
        int x0 = xx + SHIFTS; if (x0 >= IMG) x0 -= IMG;
        tsrc[tid] = b * (IMG * IMG) + y0 * IMG + x0;
        int rc = (y <= 48) ? 0 : ((y <= 52) ? 1 : 2);
        regid[tid] = (xx <= 48) ? rc * 3 : ((xx >= 53) ? rc * 3 + 2 : 0);
    }
    __syncthreads();

    float* kw = kh + h * (SWIN * KPAD);
    float* vw = vh + h * (SWIN * VPAD);
    {
        const int hc = h * 32 + lane;
        for (int s = 0; s < SWIN; s++) {
            size_t g = (size_t)tsrc[s] * (3 * CDIM);
            kw[s * KPAD + lane] = qkv[g + CDIM     + hc];
            vw[s * VPAD + lane] = qkv[g + 2 * CDIM + hc];
        }
    }
    __syncwarp();

    const int t1  = lane;
    const int t2  = lane + 32;
    const bool v2 = (t2 < SWIN);
    const int t2c = v2 ? t2 : 48;
    const int it1 = t1 / 7,  jt1 = t1 - it1 * 7;
    const int it2 = t2c / 7, jt2 = t2c - it2 * 7;
    const int r1  = regid[t1];
    const int r2  = regid[t2c];

    for (int s = 0; s < SWIN; s++) {
        float qd = qkv[(size_t)tsrc[s] * (3 * CDIM) + h * 32 + lane] * QSCALE;

        float a1 = 0.f, a2 = 0.f;
        #pragma unroll
        for (int d4 = 0; d4 < 8; d4++) {
            float4 k1 = *(const float4*)&kw[t1  * KPAD + d4 * 4];
            float4 k2 = *(const float4*)&kw[t2c * KPAD + d4 * 4];
            float q0 = __shfl_sync(0xffffffffu, qd, d4 * 4 + 0);
            float q1 = __shfl_sync(0xffffffffu, qd, d4 * 4 + 1);
            float q2 = __shfl_sync(0xffffffffu, qd, d4 * 4 + 2);
            float q3 = __shfl_sync(0xffffffffu, qd, d4 * 4 + 3);
            a1 = fmaf(q0, k1.x, a1); a1 = fmaf(q1, k1.y, a1);
            a1 = fmaf(q2, k1.z, a1); a1 = fmaf(q3, k1.w, a1);
            a2 = fmaf(q0, k2.x, a2); a2 = fmaf(q1, k2.y, a2);
            a2 = fmaf(q2, k2.z, a2); a2 = fmaf(q3, k2.w, a2);
        }

        int i1 = s / 7, j1 = s - i1 * 7;
        int rs = regid[s];
        {
            int ridx = (i1 - it1 + 6) * 13 + (j1 - jt1 + 6);
            a1 += btab[ridx * NHEAD + h];
            if (rs != r1) a1 -= 100.0f;
        }
        if (v2) {
            int ridx = (i1 - it2 + 6) * 13 + (j1 - jt2 + 6);
            a2 += btab[ridx * NHEAD + h];
            if (rs != r2) a2 -= 100.0f;
        } else {
            a2 = -1e30f;
        }

        float m = fmaxf(a1, a2);
        #pragma unroll
        for (int o = 16; o; o >>= 1) m = fmaxf(m, __shfl_xor_sync(0xffffffffu, m, o));
        float e1 = __expf(a1 - m);
        float e2 = v2 ? __expf(a2 - m) : 0.0f;
        float sum = e1 + e2;
        #pragma unroll
        for (int o = 16; o; o >>= 1) sum += __shfl_xor_sync(0xffffffffu, sum, o);
        float inv = 1.0f / sum;
        float p1 = e1 * inv;
        float p2 = e2 * inv;

        float oa = 0.f;
        #pragma unroll
        for (int t = 0; t < 32; t++) {
            float av = __shfl_sync(0xffffffffu, p1, t);
            oa = fmaf(av, vw[t * VPAD + lane], oa);
        }
        #pragma unroll
        for (int t = 32; t < SWIN; t++) {
            float av = __shfl_sync(0xffffffffu, p2, t - 32);
            oa = fmaf(av, vw[t * VPAD + lane], oa);
        }
        o_h[(size_t)tsrc[s] * CDIM + h * 32 + lane] = __float2half_rn(oa);
    }
}

// ---------------- launch ----------------
extern "C" void kernel_launch(void* const* d_in, const int* in_sizes, int n_in,
                              void* d_out, int out_size)
{
    const float* x      = (const float*)d_in[0];
    const float* gamma  = (const float*)d_in[1];
    const float* beta   = (const float*)d_in[2];
    const float* qkv_w  = (const float*)d_in[3];
    const float* qkv_b  = (const float*)d_in[4];
    const float* proj_w = (const float*)d_in[5];
    const float* proj_b = (const float*)d_in[6];
    const float* btab   = (const float*)d_in[7];
    const float* w1     = (const float*)d_in[8];
    const float* b1     = (const float*)d_in[9];
    const float* w2     = (const float*)d_in[10];
    const float* b2     = (const float*)d_in[11];
    float* out = (float*)d_out;

    __half *xnh, *oh, *xn2h, *hh, *wq, *wp, *w1h, *w2h;
    float *qkv, *x1;
    cudaGetSymbolAddress((void**)&xnh,  g_xnh);
    cudaGetSymbolAddress((void**)&oh,   g_oh);
    cudaGetSymbolAddress((void**)&xn2h, g_xn2h);
    cudaGetSymbolAddress((void**)&hh,   g_hh);
    cudaGetSymbolAddress((void**)&wq,   g_wq);
    cudaGetSymbolAddress((void**)&wp,   g_wp);
    cudaGetSymbolAddress((void**)&w1h,  g_w1h);
    cudaGetSymbolAddress((void**)&w2h,  g_w2h);
    cudaGetSymbolAddress((void**)&qkv,  g_qkv);
    cudaGetSymbolAddress((void**)&x1,   g_x1);

    cudaFuncSetAttribute(hgemm1<0>, cudaFuncAttributeMaxDynamicSharedMemorySize, HG_SMEM);
    cudaFuncSetAttribute(hgemm1<1>, cudaFuncAttributeMaxDynamicSharedMemorySize, HG_SMEM);
    cudaFuncSetAttribute(hgemm1<2>, cudaFuncAttributeMaxDynamicSharedMemorySize, HG_SMEM);
    cudaFuncSetAttribute(attn_kernel, cudaFuncAttributeMaxDynamicSharedMemorySize, ATT_SMEM);

    // weight prep (fp16 transpose to [N,K])
    wprep_t<<<(CDIM * 3 * CDIM + 255) / 256, 256>>>(qkv_w,  wq,  CDIM, 3 * CDIM);
    wprep_t<<<(CDIM * CDIM     + 255) / 256, 256>>>(proj_w, wp,  CDIM, CDIM);
    wprep_t<<<(CDIM * NMLP     + 255) / 256, 256>>>(w1,     w1h, CDIM, NMLP);
    wprep_t<<<(NMLP * CDIM     + 255) / 256, 256>>>(w2,     w2h, NMLP, CDIM);

    // 1) LN1(x) -> fp16
    ln_h_kernel<<<NTOK / 8, 256>>>(x, gamma, beta, xnh);
    // 2) qkv = xn @ qkv_w + qkv_b   (fp32 out)
    hgemm1<2><<<dim3(3 * CDIM / 128, NTOK / 128), 256, HG_SMEM>>>(
        xnh, wq, qkv_b, nullptr, qkv, nullptr, NTOK, 3 * CDIM, CDIM);
    // 3) windowed attention -> fp16
    attn_kernel<<<BATCH * NWIN, 256, ATT_SMEM>>>(qkv, btab, oh);
    // 4) x1 = x + o @ proj_w + proj_b
    hgemm1<1><<<dim3(CDIM / 128, NTOK / 128), 256, HG_SMEM>>>(
        oh, wp, proj_b, x, x1, nullptr, NTOK, CDIM, CDIM);
    // 5) LN2(x1) -> fp16
    ln_h_kernel<<<NTOK / 8, 256>>>(x1, gamma, beta, xn2h);
    // 6) h = gelu(xn2 @ w1 + b1) -> fp16
    hgemm1<0><<<dim3(NMLP / 128, NTOK / 128), 256, HG_SMEM>>>(
        xn2h, w1h, b1, nullptr, nullptr, hh, NTOK, NMLP, CDIM);
    // 7) out = x1 + h @ w2 + b2
    hgemm1<1><<<dim3(CDIM / 128, NTOK / 128), 256, HG_SMEM>>>(
        hh, w2h, b2, x1, out, nullptr, NTOK, CDIM, NMLP);
}

// round 10
// speedup vs baseline: 1.4624x; 1.4624x over previous
#include <cuda_runtime.h>
#include <cuda_fp16.h>
#include <cstdint>
#include <cstddef>

// ---------------- static problem config ----------------
#define IMG    56
#define WIN    7
#define SHIFTS 3
#define CDIM   256
#define NHEAD  8
#define DHEAD  32
#define SWIN   49
#define NWIN   64
#define NMLP   1024
#define BATCH  32
#define NTOK   (BATCH*IMG*IMG)           // 100352
#define QSCALE 0.17677669529663689f
#define APITCH 320                       // 640B rows: avoids bit-9 L2-slice collision

// ---------------- scratch (device globals) ----------------
__device__ __half g_xnh [(size_t)NTOK * APITCH];   // LN1 out fp16 (pitched)
__device__ __half g_oh  [(size_t)NTOK * APITCH];   // attn out fp16 (pitched)
__device__ __half g_xn2h[(size_t)NTOK * APITCH];   // LN2 out fp16 (pitched)
__device__ __half g_hh  [(size_t)NTOK * NMLP];     // gelu out fp16 (2KB rows, safe)
__device__ float  g_qkv [(size_t)NTOK * 3 * CDIM]; // qkv fp32
__device__ float  g_x1  [(size_t)NTOK * CDIM];     // x + attn
__device__ __half g_wq  [(size_t)(3*CDIM) * APITCH]; // weights [N,K] fp16 (pitched)
__device__ __half g_wp  [(size_t)CDIM * APITCH];
__device__ __half g_w1h [(size_t)NMLP * APITCH];
__device__ __half g_w2h [(size_t)CDIM * NMLP];       // 2KB rows, safe

// ---------------- helpers ----------------
__device__ __forceinline__ float gelu_exact(float v) {
    return 0.5f * v * (1.0f + erff(v * 0.70710678118654752f));
}
__device__ __forceinline__ uint32_t smem_u32(const void* p) {
    uint32_t a;
    asm("{ .reg .u64 t; cvta.to.shared.u64 t, %1; cvt.u32.u64 %0, t; }"
        : "=r"(a) : "l"(p));
    return a;
}
__device__ __forceinline__ void ldsm4(uint32_t* r, uint32_t addr) {
    asm volatile("ldmatrix.sync.aligned.m8n8.x4.shared.b16 {%0,%1,%2,%3}, [%4];"
        : "=r"(r[0]), "=r"(r[1]), "=r"(r[2]), "=r"(r[3]) : "r"(addr));
}
__device__ __forceinline__ void mma16816(float* c, const uint32_t* a,
                                         uint32_t b0, uint32_t b1) {
    asm volatile("mma.sync.aligned.m16n8k16.row.col.f32.f16.f16.f32 "
        "{%0,%1,%2,%3}, {%4,%5,%6,%7}, {%8,%9}, {%0,%1,%2,%3};"
        : "+f"(c[0]), "+f"(c[1]), "+f"(c[2]), "+f"(c[3])
        : "r"(a[0]), "r"(a[1]), "r"(a[2]), "r"(a[3]), "r"(b0), "r"(b1));
}
__device__ __forceinline__ void cpa16(uint32_t s, const void* g) {
    asm volatile("cp.async.cg.shared.global [%0], [%1], 16;" :: "r"(s), "l"(g));
}
#define CP_COMMIT() asm volatile("cp.async.commit_group;" ::: "memory")
#define CP_WAIT1()  asm volatile("cp.async.wait_group 1;" ::: "memory")
#define CP_WAIT0()  asm volatile("cp.async.wait_group 0;" ::: "memory")

// ---------------- weight prep: W [K,N] fp32 -> Wh [N,ldout] fp16 ----------------
__global__ void wprep_t(const float* __restrict__ W, __half* __restrict__ Wh,
                        int K, int N, int ldout)
{
    int idx = blockIdx.x * 256 + threadIdx.x;
    if (idx >= K * N) return;
    int k = idx / N, n = idx - k * N;
    Wh[(size_t)n * ldout + k] = __float2half_rn(W[idx]);
}

// ---------------- LayerNorm -> fp16 (pitched): one warp per token ----------------
__global__ __launch_bounds__(256) void ln_h_kernel(
    const float* __restrict__ x,
    const float* __restrict__ gamma,
    const float* __restrict__ beta,
    __half* __restrict__ outh)   // [NTOK, APITCH] fp16
{
    int lane = threadIdx.x & 31;
    int warp = threadIdx.x >> 5;
    int tok  = blockIdx.x * 8 + warp;

    const float4* px = (const float4*)(x + (size_t)tok * CDIM);
    float4 v0 = px[lane];
    float4 v1 = px[lane + 32];

    float s  = v0.x + v0.y + v0.z + v0.w + v1.x + v1.y + v1.z + v1.w;
    float ss = v0.x*v0.x + v0.y*v0.y + v0.z*v0.z + v0.w*v0.w
             + v1.x*v1.x + v1.y*v1.y + v1.z*v1.z + v1.w*v1.w;
    #pragma unroll
    for (int o = 16; o; o >>= 1) {
        s  += __shfl_xor_sync(0xffffffffu, s,  o);
        ss += __shfl_xor_sync(0xffffffffu, ss, o);
    }
    float mu  = s * (1.0f / 256.0f);
    float var = ss * (1.0f / 256.0f) - mu * mu;
    float rs  = rsqrtf(var + 1e-5f);

    const float4* pg = (const float4*)gamma;
    const float4* pb = (const float4*)beta;
    float4 g0 = pg[lane], g1 = pg[lane + 32];
    float4 b0 = pb[lane], b1 = pb[lane + 32];

    __half2 o0, o1, o2, o3;
    o0.x = __float2half_rn((v0.x - mu) * rs * g0.x + b0.x);
    o0.y = __float2half_rn((v0.y - mu) * rs * g0.y + b0.y);
    o1.x = __float2half_rn((v0.z - mu) * rs * g0.z + b0.z);
    o1.y = __float2half_rn((v0.w - mu) * rs * g0.w + b0.w);
    o2.x = __float2half_rn((v1.x - mu) * rs * g1.x + b1.x);
    o2.y = __float2half_rn((v1.y - mu) * rs * g1.y + b1.y);
    o3.x = __float2half_rn((v1.z - mu) * rs * g1.z + b1.z);
    o3.y = __float2half_rn((v1.w - mu) * rs * g1.w + b1.w);

    __half* base = outh + (size_t)tok * APITCH;
    *(__half2*)(base + lane * 4)           = o0;
    *(__half2*)(base + lane * 4 + 2)       = o1;
    *(__half2*)(base + 128 + lane * 4)     = o2;
    *(__half2*)(base + 128 + lane * 4 + 2) = o3;
}

// ---------------- HMMA GEMM: 128x128 tile, BK=64, plain fp16, pitched A/B ----------------
// A [M, lda] fp16, Bw [N, ldb] fp16.
// EPI 0: outh = fp16(gelu(acc + bias)); EPI 1: outf = res + acc + bias; EPI 2: outf = acc + bias
#define HG_SMEM 65536

template<int EPI>
__global__ __launch_bounds__(256, 2) void hgemm1(
    const __half* __restrict__ A,
    const __half* __restrict__ Bw,
    const float* __restrict__ bias,
    const float* __restrict__ res,
    float* __restrict__ outf,
    __half* __restrict__ outh,
    int M, int N, int K, int lda, int ldb)
{
    extern __shared__ char smem[];
    const uint32_t sAb = smem_u32(smem);            // 2 x 16KB
    const uint32_t sBb = sAb + 32768;               // 2 x 16KB

    const int tid  = threadIdx.x;
    const int lane = tid & 31;
    const int wid  = tid >> 5;
    const int wm   = wid >> 1;       // 0..3
    const int wn   = wid & 1;        // 0..1
    const int row0 = blockIdx.y * 128;
    const int col0 = blockIdx.x * 128;
    const int nch  = K / 64;

    float acc[2][8][4];
    #pragma unroll
    for (int a = 0; a < 2; a++)
        #pragma unroll
        for (int b = 0; b < 8; b++)
            #pragma unroll
            for (int c = 0; c < 4; c++) acc[a][b][c] = 0.f;

    auto issue = [&](int g) {
        uint32_t sa = sAb + (g & 1) * 16384;
        uint32_t sb = sBb + (g & 1) * 16384;
        #pragma unroll
        for (int i = 0; i < 4; i++) {
            int id = tid + i * 256;
            int r = id >> 3, kg = id & 7;
            int sg = kg ^ (r & 7);
            uint32_t so = (uint32_t)(r * 128 + sg * 16);
            cpa16(sa + so, A  + (size_t)(row0 + r) * lda + g * 64 + kg * 8);
            cpa16(sb + so, Bw + (size_t)(col0 + r) * ldb + g * 64 + kg * 8);
        }
        CP_COMMIT();
    };

    issue(0);
    for (int g = 0; g < nch; g++) {
        if (g + 1 < nch) { issue(g + 1); CP_WAIT1(); }
        else             { CP_WAIT0(); }
        __syncthreads();

        const uint32_t aB = sAb + (g & 1) * 16384;
        const uint32_t bB = sBb + (g & 1) * 16384;
        #pragma unroll
        for (int kt = 0; kt < 4; kt++) {
            uint32_t a[2][4], b[4][4];
            const int kg = kt * 2 + (lane >> 4);
            #pragma unroll
            for (int mt = 0; mt < 2; mt++) {
                int r  = wm * 32 + mt * 16 + (lane & 15);
                int sg = kg ^ (r & 7);
                ldsm4(a[mt], aB + (uint32_t)(r * 128 + sg * 16));
            }
            #pragma unroll
            for (int nb = 0; nb < 4; nb++) {
                int r  = wn * 64 + nb * 16 + (lane & 15);
                int sg = kg ^ (r & 7);
                ldsm4(b[nb], bB + (uint32_t)(r * 128 + sg * 16));
            }
            #pragma unroll
            for (int mt = 0; mt < 2; mt++)
                #pragma unroll
                for (int nb = 0; nb < 4; nb++) {
                    mma16816(acc[mt][2 * nb],     a[mt], b[nb][0], b[nb][2]);
                    mma16816(acc[mt][2 * nb + 1], a[mt], b[nb][1], b[nb][3]);
                }
        }
        __syncthreads();
    }

    // epilogue
    const int g4 = lane >> 2, q = lane & 3;
    #pragma unroll
    for (int mt = 0; mt < 2; mt++) {
        #pragma unroll
        for (int half = 0; half < 2; half++) {
            int row = row0 + wm * 32 + mt * 16 + g4 + half * 8;
            #pragma unroll
            for (int nt = 0; nt < 8; nt++) {
                int col = col0 + wn * 64 + nt * 8 + q * 2;
                float v0 = acc[mt][nt][half * 2 + 0] + bias[col];
                float v1 = acc[mt][nt][half * 2 + 1] + bias[col + 1];
                if (EPI == 2) {
                    *(float2*)(outf + (size_t)row * N + col) = make_float2(v0, v1);
                } else if (EPI == 1) {
                    const float2 rv = *(const float2*)(res + (size_t)row * N + col);
                    *(float2*)(outf + (size_t)row * N + col) =
                        make_float2(v0 + rv.x, v1 + rv.y);
                } else {
                    __half2 hp;
                    hp.x = __float2half_rn(gelu_exact(v0));
                    hp.y = __float2half_rn(gelu_exact(v1));
                    *(__half2*)(outh + (size_t)row * N + col) = hp;
                }
            }
        }
    }
}

// ---------------- attention: one CTA per window, one warp per head ----------------
#define KPAD 36
#define VPAD 33
#define SM_KH   0
#define SM_VH   (NHEAD*SWIN*KPAD)
#define SM_AINT (SM_VH + NHEAD*SWIN*VPAD)
#define ATT_SMEM ((SM_AINT + 2*SWIN) * 4)

__global__ __launch_bounds__(256) void attn_kernel(
    const float* __restrict__ qkv,    // [NTOK, 768] (q|k|v)
    const float* __restrict__ btab,   // [169, 8]
    __half* __restrict__ o_h)         // [NTOK, APITCH] fp16
{
    extern __shared__ float sm[];
    float* kh  = sm + SM_KH;
    float* vh  = sm + SM_VH;
    int* tsrc  = (int*)(sm + SM_AINT);
    int* regid = tsrc + SWIN;

    const int tid  = threadIdx.x;
    const int lane = tid & 31;
    const int h    = tid >> 5;

    const int win = blockIdx.x;
    const int b   = win >> 6;
    const int wq  = win & 63;
    const int wy  = wq >> 3;
    const int wx  = wq & 7;

    if (tid < SWIN) {
        int i = tid / 7, j = tid - i * 7;
        int y  = wy * 7 + i;
        int xx = wx * 7 + j;
        int y0 = y  + SHIFTS; if (y0 >= IMG) y0 -= IMG;
        int x0 = xx + SHIFTS; if (x0 >= IMG) x0 -= IMG;
        tsrc[tid] = b * (IMG * IMG) + y0 * IMG + x0;
        int rc = (y <= 48) ? 0 : ((y <= 52) ? 1 : 2);
        regid[tid] = (xx <= 48) ? rc * 3 : ((xx >= 53) ? rc * 3 + 2 : 0);
    }
    __syncthreads();

    float* kw = kh + h * (SWIN * KPAD);
    float* vw = vh + h * (SWIN * VPAD);
    {
        const int hc = h * 32 + lane;
        for (int s = 0; s < SWIN; s++) {
            size_t g = (size_t)tsrc[s] * (3 * CDIM);
            kw[s * KPAD + lane] = qkv[g + CDIM     + hc];
            vw[s * VPAD + lane] = qkv[g + 2 * CDIM + hc];
        }
    }
    __syncwarp();

    const int t1  = lane;
    const int t2  = lane + 32;
    const bool v2 = (t2 < SWIN);
    const int t2c = v2 ? t2 : 48;
    const int it1 = t1 / 7,  jt1 = t1 - it1 * 7;
    const int it2 = t2c / 7, jt2 = t2c - it2 * 7;
    const int r1  = regid[t1];
    const int r2  = regid[t2c];

    for (int s = 0; s < SWIN; s++) {
        float qd = qkv[(size_t)tsrc[s] * (3 * CDIM) + h * 32 + lane] * QSCALE;

        float a1 = 0.f, a2 = 0.f;
        #pragma unroll
        for (int d4 = 0; d4 < 8; d4++) {
            float4 k1 = *(const float4*)&kw[t1  * KPAD + d4 * 4];
            float4 k2 = *(const float4*)&kw[t2c * KPAD + d4 * 4];
            float q0 = __shfl_sync(0xffffffffu, qd, d4 * 4 + 0);
            float q1 = __shfl_sync(0xffffffffu, qd, d4 * 4 + 1);
            float q2 = __shfl_sync(0xffffffffu, qd, d4 * 4 + 2);
            float q3 = __shfl_sync(0xffffffffu, qd, d4 * 4 + 3);
            a1 = fmaf(q0, k1.x, a1); a1 = fmaf(q1, k1.y, a1);
            a1 = fmaf(q2, k1.z, a1); a1 = fmaf(q3, k1.w, a1);
            a2 = fmaf(q0, k2.x, a2); a2 = fmaf(q1, k2.y, a2);
            a2 = fmaf(q2, k2.z, a2); a2 = fmaf(q3, k2.w, a2);
        }

        int i1 = s / 7, j1 = s - i1 * 7;
        int rs = regid[s];
        {
            int ridx = (i1 - it1 + 6) * 13 + (j1 - jt1 + 6);
            a1 += btab[ridx * NHEAD + h];
            if (rs != r1) a1 -= 100.0f;
        }
        if (v2) {
            int ridx = (i1 - it2 + 6) * 13 + (j1 - jt2 + 6);
            a2 += btab[ridx * NHEAD + h];
            if (rs != r2) a2 -= 100.0f;
        } else {
            a2 = -1e30f;
        }

        float m = fmaxf(a1, a2);
        #pragma unroll
        for (int o = 16; o; o >>= 1) m = fmaxf(m, __shfl_xor_sync(0xffffffffu, m, o));
        float e1 = __expf(a1 - m);
        float e2 = v2 ? __expf(a2 - m) : 0.0f;
        float sum = e1 + e2;
        #pragma unroll
        for (int o = 16; o; o >>= 1) sum += __shfl_xor_sync(0xffffffffu, sum, o);
        float inv = 1.0f / sum;
        float p1 = e1 * inv;
        float p2 = e2 * inv;

        float oa = 0.f;
        #pragma unroll
        for (int t = 0; t < 32; t++) {
            float av = __shfl_sync(0xffffffffu, p1, t);
            oa = fmaf(av, vw[t * VPAD + lane], oa);
        }
        #pragma unroll
        for (int t = 32; t < SWIN; t++) {
            float av = __shfl_sync(0xffffffffu, p2, t - 32);
            oa = fmaf(av, vw[t * VPAD + lane], oa);
        }
        o_h[(size_t)tsrc[s] * APITCH + h * 32 + lane] = __float2half_rn(oa);
    }
}

// ---------------- launch ----------------
extern "C" void kernel_launch(void* const* d_in, const int* in_sizes, int n_in,
                              void* d_out, int out_size)
{
    const float* x      = (const float*)d_in[0];
    const float* gamma  = (const float*)d_in[1];
    const float* beta   = (const float*)d_in[2];
    const float* qkv_w  = (const float*)d_in[3];
    const float* qkv_b  = (const float*)d_in[4];
    const float* proj_w = (const float*)d_in[5];
    const float* proj_b = (const float*)d_in[6];
    const float* btab   = (const float*)d_in[7];
    const float* w1     = (const float*)d_in[8];
    const float* b1     = (const float*)d_in[9];
    const float* w2     = (const float*)d_in[10];
    const float* b2     = (const float*)d_in[11];
    float* out = (float*)d_out;

    __half *xnh, *oh, *xn2h, *hh, *wq, *wp, *w1h, *w2h;
    float *qkv, *x1;
    cudaGetSymbolAddress((void**)&xnh,  g_xnh);
    cudaGetSymbolAddress((void**)&oh,   g_oh);
    cudaGetSymbolAddress((void**)&xn2h, g_xn2h);
    cudaGetSymbolAddress((void**)&hh,   g_hh);
    cudaGetSymbolAddress((void**)&wq,   g_wq);
    cudaGetSymbolAddress((void**)&wp,   g_wp);
    cudaGetSymbolAddress((void**)&w1h,  g_w1h);
    cudaGetSymbolAddress((void**)&w2h,  g_w2h);
    cudaGetSymbolAddress((void**)&qkv,  g_qkv);
    cudaGetSymbolAddress((void**)&x1,   g_x1);

    cudaFuncSetAttribute(hgemm1<0>, cudaFuncAttributeMaxDynamicSharedMemorySize, HG_SMEM);
    cudaFuncSetAttribute(hgemm1<1>, cudaFuncAttributeMaxDynamicSharedMemorySize, HG_SMEM);
    cudaFuncSetAttribute(hgemm1<2>, cudaFuncAttributeMaxDynamicSharedMemorySize, HG_SMEM);
    cudaFuncSetAttribute(attn_kernel, cudaFuncAttributeMaxDynamicSharedMemorySize, ATT_SMEM);

    // weight prep (fp16 transpose, pitched)
    wprep_t<<<(CDIM * 3 * CDIM + 255) / 256, 256>>>(qkv_w,  wq,  CDIM, 3 * CDIM, APITCH);
    wprep_t<<<(CDIM * CDIM     + 255) / 256, 256>>>(proj_w, wp,  CDIM, CDIM,     APITCH);
    wprep_t<<<(CDIM * NMLP     + 255) / 256, 256>>>(w1,     w1h, CDIM, NMLP,     APITCH);
    wprep_t<<<(NMLP * CDIM     + 255) / 256, 256>>>(w2,     w2h, NMLP, CDIM,     NMLP);

    // 1) LN1(x) -> fp16 (pitched)
    ln_h_kernel<<<NTOK / 8, 256>>>(x, gamma, beta, xnh);
    // 2) qkv = xn @ qkv_w + qkv_b   (fp32 out)
    hgemm1<2><<<dim3(3 * CDIM / 128, NTOK / 128), 256, HG_SMEM>>>(
        xnh, wq, qkv_b, nullptr, qkv, nullptr, NTOK, 3 * CDIM, CDIM, APITCH, APITCH);
    // 3) windowed attention -> fp16 (pitched)
    attn_kernel<<<BATCH * NWIN, 256, ATT_SMEM>>>(qkv, btab, oh);
    // 4) x1 = x + o @ proj_w + proj_b
    hgemm1<1><<<dim3(CDIM / 128, NTOK / 128), 256, HG_SMEM>>>(
        oh, wp, proj_b, x, x1, nullptr, NTOK, CDIM, CDIM, APITCH, APITCH);
    // 5) LN2(x1) -> fp16 (pitched)
    ln_h_kernel<<<NTOK / 8, 256>>>(x1, gamma, beta, xn2h);
    // 6) h = gelu(xn2 @ w1 + b1) -> fp16 (2KB rows)
    hgemm1<0><<<dim3(NMLP / 128, NTOK / 128), 256, HG_SMEM>>>(
        xn2h, w1h, b1, nullptr, nullptr, hh, NTOK, NMLP, CDIM, APITCH, APITCH);
    // 7) out = x1 + h @ w2 + b2
    hgemm1<1><<<dim3(CDIM / 128, NTOK / 128), 256, HG_SMEM>>>(
        hh, w2h, b2, x1, out, nullptr, NTOK, CDIM, NMLP, NMLP, NMLP);
}

// round 11
// speedup vs baseline: 1.9507x; 1.3339x over previous
#include <cuda_runtime.h>
#include <cuda_fp16.h>
#include <cstdint>
#include <cstddef>

// ---------------- static problem config ----------------
#define IMG    56
#define WIN    7
#define SHIFTS 3
#define CDIM   256
#define NHEAD  8
#define DHEAD  32
#define SWIN   49
#define NWIN   64
#define NMLP   1024
#define BATCH  32
#define NTOK   (BATCH*IMG*IMG)           // 100352
#define QSCALE 0.17677669529663689f
#define APITCH 320                       // 640B rows: avoids bit-9 L2-slice collision
#define QKVDIM (3*CDIM)                  // 768 (1536B rows; stride safe per hash analysis)

// ---------------- scratch (device globals) ----------------
__device__ __half g_xnh [(size_t)NTOK * APITCH];   // LN1 out fp16 (pitched)
__device__ __half g_oh  [(size_t)NTOK * APITCH];   // attn out fp16 (pitched)
__device__ __half g_xn2h[(size_t)NTOK * APITCH];   // LN2 out fp16 (pitched)
__device__ __half g_hh  [(size_t)NTOK * NMLP];     // gelu out fp16 (2KB rows, safe)
__device__ __half g_qkvh[(size_t)NTOK * QKVDIM];   // qkv fp16
__device__ float  g_x1  [(size_t)NTOK * CDIM];     // x + attn
__device__ __half g_wq  [(size_t)QKVDIM * APITCH]; // weights [N,K] fp16 (pitched)
__device__ __half g_wp  [(size_t)CDIM * APITCH];
__device__ __half g_w1h [(size_t)NMLP * APITCH];
__device__ __half g_w2h [(size_t)CDIM * NMLP];     // 2KB rows, safe

// ---------------- helpers ----------------
__device__ __forceinline__ float gelu_exact(float v) {
    return 0.5f * v * (1.0f + erff(v * 0.70710678118654752f));
}
__device__ __forceinline__ uint32_t smem_u32(const void* p) {
    uint32_t a;
    asm("{ .reg .u64 t; cvta.to.shared.u64 t, %1; cvt.u32.u64 %0, t; }"
        : "=r"(a) : "l"(p));
    return a;
}
__device__ __forceinline__ void ldsm4(uint32_t* r, uint32_t addr) {
    asm volatile("ldmatrix.sync.aligned.m8n8.x4.shared.b16 {%0,%1,%2,%3}, [%4];"
        : "=r"(r[0]), "=r"(r[1]), "=r"(r[2]), "=r"(r[3]) : "r"(addr));
}
__device__ __forceinline__ void mma16816(float* c, const uint32_t* a,
                                         uint32_t b0, uint32_t b1) {
    asm volatile("mma.sync.aligned.m16n8k16.row.col.f32.f16.f16.f32 "
        "{%0,%1,%2,%3}, {%4,%5,%6,%7}, {%8,%9}, {%0,%1,%2,%3};"
        : "+f"(c[0]), "+f"(c[1]), "+f"(c[2]), "+f"(c[3])
        : "r"(a[0]), "r"(a[1]), "r"(a[2]), "r"(a[3]), "r"(b0), "r"(b1));
}
__device__ __forceinline__ void cpa16(uint32_t s, const void* g) {
    asm volatile("cp.async.cg.shared.global [%0], [%1], 16;" :: "r"(s), "l"(g));
}
#define CP_COMMIT() asm volatile("cp.async.commit_group;" ::: "memory")
#define CP_WAIT1()  asm volatile("cp.async.wait_group 1;" ::: "memory")
#define CP_WAIT0()  asm volatile("cp.async.wait_group 0;" ::: "memory")

// ---------------- weight prep: W [K,N] fp32 -> Wh [N,ldout] fp16 ----------------
__global__ void wprep_t(const float* __restrict__ W, __half* __restrict__ Wh,
                        int K, int N, int ldout)
{
    int idx = blockIdx.x * 256 + threadIdx.x;
    if (idx >= K * N) return;
    int k = idx / N, n = idx - k * N;
    Wh[(size_t)n * ldout + k] = __float2half_rn(W[idx]);
}

// ---------------- LayerNorm -> fp16 (pitched): one warp per token ----------------
__global__ __launch_bounds__(256) void ln_h_kernel(
    const float* __restrict__ x,
    const float* __restrict__ gamma,
    const float* __restrict__ beta,
    __half* __restrict__ outh)   // [NTOK, APITCH] fp16
{
    int lane = threadIdx.x & 31;
    int warp = threadIdx.x >> 5;
    int tok  = blockIdx.x * 8 + warp;

    const float4* px = (const float4*)(x + (size_t)tok * CDIM);
    float4 v0 = px[lane];
    float4 v1 = px[lane + 32];

    float s  = v0.x + v0.y + v0.z + v0.w + v1.x + v1.y + v1.z + v1.w;
    float ss = v0.x*v0.x + v0.y*v0.y + v0.z*v0.z + v0.w*v0.w
             + v1.x*v1.x + v1.y*v1.y + v1.z*v1.z + v1.w*v1.w;
    #pragma unroll
    for (int o = 16; o; o >>= 1) {
        s  += __shfl_xor_sync(0xffffffffu, s,  o);
        ss += __shfl_xor_sync(0xffffffffu, ss, o);
    }
    float mu  = s * (1.0f / 256.0f);
    float var = ss * (1.0f / 256.0f) - mu * mu;
    float rs  = rsqrtf(var + 1e-5f);

    const float4* pg = (const float4*)gamma;
    const float4* pb = (const float4*)beta;
    float4 g0 = pg[lane], g1 = pg[lane + 32];
    float4 b0 = pb[lane], b1 = pb[lane + 32];

    __half2 o0, o1, o2, o3;
    o0.x = __float2half_rn((v0.x - mu) * rs * g0.x + b0.x);
    o0.y = __float2half_rn((v0.y - mu) * rs * g0.y + b0.y);
    o1.x = __float2half_rn((v0.z - mu) * rs * g0.z + b0.z);
    o1.y = __float2half_rn((v0.w - mu) * rs * g0.w + b0.w);
    o2.x = __float2half_rn((v1.x - mu) * rs * g1.x + b1.x);
    o2.y = __float2half_rn((v1.y - mu) * rs * g1.y + b1.y);
    o3.x = __float2half_rn((v1.z - mu) * rs * g1.z + b1.z);
    o3.y = __float2half_rn((v1.w - mu) * rs * g1.w + b1.w);

    __half* base = outh + (size_t)tok * APITCH;
    *(__half2*)(base + lane * 4)           = o0;
    *(__half2*)(base + lane * 4 + 2)       = o1;
    *(__half2*)(base + 128 + lane * 4)     = o2;
    *(__half2*)(base + 128 + lane * 4 + 2) = o3;
}

// ---------------- HMMA GEMM: 128x128 tile, BK=64, plain fp16, pitched A/B ----------------
// EPI 0: outh = fp16(gelu(acc+bias)); EPI 1: outf = res+acc+bias;
// EPI 2: outf = acc+bias;             EPI 3: outh = fp16(acc+bias)
#define HG_SMEM 65536

template<int EPI>
__global__ __launch_bounds__(256, 2) void hgemm1(
    const __half* __restrict__ A,
    const __half* __restrict__ Bw,
    const float* __restrict__ bias,
    const float* __restrict__ res,
    float* __restrict__ outf,
    __half* __restrict__ outh,
    int M, int N, int K, int lda, int ldb)
{
    extern __shared__ char smem[];
    const uint32_t sAb = smem_u32(smem);            // 2 x 16KB
    const uint32_t sBb = sAb + 32768;               // 2 x 16KB

    const int tid  = threadIdx.x;
    const int lane = tid & 31;
    const int wid  = tid >> 5;
    const int wm   = wid >> 1;       // 0..3
    const int wn   = wid & 1;        // 0..1
    const int row0 = blockIdx.y * 128;
    const int col0 = blockIdx.x * 128;
    const int nch  = K / 64;

    float acc[2][8][4];
    #pragma unroll
    for (int a = 0; a < 2; a++)
        #pragma unroll
        for (int b = 0; b < 8; b++)
            #pragma unroll
            for (int c = 0; c < 4; c++) acc[a][b][c] = 0.f;

    auto issue = [&](int g) {
        uint32_t sa = sAb + (g & 1) * 16384;
        uint32_t sb = sBb + (g & 1) * 16384;
        #pragma unroll
        for (int i = 0; i < 4; i++) {
            int id = tid + i * 256;
            int r = id >> 3, kg = id & 7;
            int sg = kg ^ (r & 7);
            uint32_t so = (uint32_t)(r * 128 + sg * 16);
            cpa16(sa + so, A  + (size_t)(row0 + r) * lda + g * 64 + kg * 8);
            cpa16(sb + so, Bw + (size_t)(col0 + r) * ldb + g * 64 + kg * 8);
        }
        CP_COMMIT();
    };

    issue(0);
    for (int g = 0; g < nch; g++) {
        if (g + 1 < nch) { issue(g + 1); CP_WAIT1(); }
        else             { CP_WAIT0(); }
        __syncthreads();

        const uint32_t aB = sAb + (g & 1) * 16384;
        const uint32_t bB = sBb + (g & 1) * 16384;
        #pragma unroll
        for (int kt = 0; kt < 4; kt++) {
            uint32_t a[2][4], b[4][4];
            const int kg = kt * 2 + (lane >> 4);
            #pragma unroll
            for (int mt = 0; mt < 2; mt++) {
                int r  = wm * 32 + mt * 16 + (lane & 15);
                int sg = kg ^ (r & 7);
                ldsm4(a[mt], aB + (uint32_t)(r * 128 + sg * 16));
            }
            #pragma unroll
            for (int nb = 0; nb < 4; nb++) {
                int r  = wn * 64 + nb * 16 + (lane & 15);
                int sg = kg ^ (r & 7);
                ldsm4(b[nb], bB + (uint32_t)(r * 128 + sg * 16));
            }
            #pragma unroll
            for (int mt = 0; mt < 2; mt++)
                #pragma unroll
                for (int nb = 0; nb < 4; nb++) {
                    mma16816(acc[mt][2 * nb],     a[mt], b[nb][0], b[nb][2]);
                    mma16816(acc[mt][2 * nb + 1], a[mt], b[nb][1], b[nb][3]);
                }
        }
        __syncthreads();
    }

    // epilogue
    const int g4 = lane >> 2, q = lane & 3;
    #pragma unroll
    for (int mt = 0; mt < 2; mt++) {
        #pragma unroll
        for (int half = 0; half < 2; half++) {
            int row = row0 + wm * 32 + mt * 16 + g4 + half * 8;
            #pragma unroll
            for (int nt = 0; nt < 8; nt++) {
                int col = col0 + wn * 64 + nt * 8 + q * 2;
                float v0 = acc[mt][nt][half * 2 + 0] + bias[col];
                float v1 = acc[mt][nt][half * 2 + 1] + bias[col + 1];
                if (EPI == 2) {
                    *(float2*)(outf + (size_t)row * N + col) = make_float2(v0, v1);
                } else if (EPI == 1) {
                    const float2 rv = *(const float2*)(res + (size_t)row * N + col);
                    *(float2*)(outf + (size_t)row * N + col) =
                        make_float2(v0 + rv.x, v1 + rv.y);
                } else if (EPI == 0) {
                    __half2 hp;
                    hp.x = __float2half_rn(gelu_exact(v0));
                    hp.y = __float2half_rn(gelu_exact(v1));
                    *(__half2*)(outh + (size_t)row * N + col) = hp;
                } else {
                    __half2 hp;
                    hp.x = __float2half_rn(v0);
                    hp.y = __float2half_rn(v1);
                    *(__half2*)(outh + (size_t)row * N + col) = hp;
                }
            }
        }
    }
}

// ---------------- attention: one CTA per window, one warp per head, fp16 staging ----------------
// smem: k fp16 [8][49][36] (28224B) + v half2 t-pairs [8][25][32] (25600B) + ints (392B)
#define KPADH 36
#define NVP   25
#define ATT_SMEM (NHEAD*SWIN*KPADH*2 + NHEAD*NVP*32*4 + 2*SWIN*4)

__global__ __launch_bounds__(256, 4) void attn_kernel(
    const __half* __restrict__ qkv,   // [NTOK, 768] fp16 (q|k|v)
    const float* __restrict__ btab,   // [169, 8]
    __half* __restrict__ o_h)         // [NTOK, APITCH] fp16
{
    extern __shared__ char smc[];
    __half*  kwh = (__half*)smc;                                   // 28224 B
    __half2* vw2 = (__half2*)(smc + NHEAD * SWIN * KPADH * 2);     // 25600 B
    int* tsrc  = (int*)(smc + NHEAD * SWIN * KPADH * 2 + NHEAD * NVP * 32 * 4);
    int* regid = tsrc + SWIN;

    const int tid  = threadIdx.x;
    const int lane = tid & 31;
    const int h    = tid >> 5;

    const int win = blockIdx.x;
    const int b   = win >> 6;
    const int wq  = win & 63;
    const int wy  = wq >> 3;
    const int wx  = wq & 7;

    if (tid < SWIN) {
        int i = tid / 7, j = tid - i * 7;
        int y  = wy * 7 + i;
        int xx = wx * 7 + j;
        int y0 = y  + SHIFTS; if (y0 >= IMG) y0 -= IMG;
        int x0 = xx + SHIFTS; if (x0 >= IMG) x0 -= IMG;
        tsrc[tid] = b * (IMG * IMG) + y0 * IMG + x0;
        int rc = (y <= 48) ? 0 : ((y <= 52) ? 1 : 2);
        regid[tid] = (xx <= 48) ? rc * 3 : ((xx >= 53) ? rc * 3 + 2 : 0);
    }
    __syncthreads();

    // stage this head's k (fp16) and v (half2 t-pairs)
    __half*  kw = kwh + h * (SWIN * KPADH);
    __half2* vw = vw2 + h * (NVP * 32);
    {
        const int hc = h * 32 + lane;
        for (int s = 0; s < SWIN; s++)
            kw[s * KPADH + lane] = qkv[(size_t)tsrc[s] * QKVDIM + CDIM + hc];
        #pragma unroll
        for (int t2 = 0; t2 < NVP; t2++) {
            __half va = qkv[(size_t)tsrc[2 * t2] * QKVDIM + 2 * CDIM + hc];
            __half vb = (2 * t2 + 1 < SWIN)
                ? qkv[(size_t)tsrc[2 * t2 + 1] * QKVDIM + 2 * CDIM + hc]
                : __float2half_rn(0.f);
            vw[t2 * 32 + lane] = __halves2half2(va, vb);
        }
    }
    __syncwarp();

    const int t1  = lane;
    const int t2  = lane + 32;
    const bool v2 = (t2 < SWIN);
    const int t2c = v2 ? t2 : 48;
    const int it1 = t1 / 7,  jt1 = t1 - it1 * 7;
    const int it2 = t2c / 7, jt2 = t2c - it2 * 7;
    const int r1  = regid[t1];
    const int r2  = regid[t2c];

    const uint2* k1p = (const uint2*)(kw + t1  * KPADH);
    const uint2* k2p = (const uint2*)(kw + t2c * KPADH);

    for (int s = 0; s < SWIN; s++) {
        float qd = __half2float(qkv[(size_t)tsrc[s] * QKVDIM + h * 32 + lane]) * QSCALE;

        float a1 = 0.f, a2 = 0.f;
        #pragma unroll
        for (int j = 0; j < 8; j++) {
            uint2 ku1 = k1p[j];
            uint2 ku2 = k2p[j];
            float2 xa = __half22float2(*(__half2*)&ku1.x);
            float2 xb = __half22float2(*(__half2*)&ku1.y);
            float2 ya = __half22float2(*(__half2*)&ku2.x);
            float2 yb = __half22float2(*(__half2*)&ku2.y);
            float q0 = __shfl_sync(0xffffffffu, qd, j * 4 + 0);
            float q1 = __shfl_sync(0xffffffffu, qd, j * 4 + 1);
            float q2 = __shfl_sync(0xffffffffu, qd, j * 4 + 2);
            float q3 = __shfl_sync(0xffffffffu, qd, j * 4 + 3);
            a1 = fmaf(q0, xa.x, a1); a1 = fmaf(q1, xa.y, a1);
            a1 = fmaf(q2, xb.x, a1); a1 = fmaf(q3, xb.y, a1);
            a2 = fmaf(q0, ya.x, a2); a2 = fmaf(q1, ya.y, a2);
            a2 = fmaf(q2, yb.x, a2); a2 = fmaf(q3, yb.y, a2);
        }

        int i1 = s / 7, j1 = s - i1 * 7;
        int rs = regid[s];
        {
            int ridx = (i1 - it1 + 6) * 13 + (j1 - jt1 + 6);
            a1 += btab[ridx * NHEAD + h];
            if (rs != r1) a1 -= 100.0f;
        }
        if (v2) {
            int ridx = (i1 - it2 + 6) * 13 + (j1 - jt2 + 6);
            a2 += btab[ridx * NHEAD + h];
            if (rs != r2) a2 -= 100.0f;
        } else {
            a2 = -1e30f;
        }

        float m = fmaxf(a1, a2);
        #pragma unroll
        for (int o = 16; o; o >>= 1) m = fmaxf(m, __shfl_xor_sync(0xffffffffu, m, o));
        float e1 = __expf(a1 - m);
        float e2 = v2 ? __expf(a2 - m) : 0.0f;
        float sum = e1 + e2;
        #pragma unroll
        for (int o = 16; o; o >>= 1) sum += __shfl_xor_sync(0xffffffffu, sum, o);
        float inv = 1.0f / sum;
        float p1 = e1 * inv;
        float p2 = e2 * inv;

        float oa = 0.f;
        #pragma unroll
        for (int t2i = 0; t2i < NVP; t2i++) {
            float2 vv = __half22float2(vw[t2i * 32 + lane]);
            const int ta = 2 * t2i, tb = 2 * t2i + 1;
            float pa = (ta < 32) ? __shfl_sync(0xffffffffu, p1, ta)
                                 : __shfl_sync(0xffffffffu, p2, ta - 32);
            float pb = (tb < 32) ? __shfl_sync(0xffffffffu, p1, tb)
                                 : __shfl_sync(0xffffffffu, p2, tb - 32);
            oa = fmaf(pa, vv.x, oa);
            oa = fmaf(pb, vv.y, oa);
        }
        o_h[(size_t)tsrc[s] * APITCH + h * 32 + lane] = __float2half_rn(oa);
    }
}

// ---------------- launch ----------------
extern "C" void kernel_launch(void* const* d_in, const int* in_sizes, int n_in,
                              void* d_out, int out_size)
{
    const float* x      = (const float*)d_in[0];
    const float* gamma  = (const float*)d_in[1];
    const float* beta   = (const float*)d_in[2];
    const float* qkv_w  = (const float*)d_in[3];
    const float* qkv_b  = (const float*)d_in[4];
    const float* proj_w = (const float*)d_in[5];
    const float* proj_b = (const float*)d_in[6];
    const float* btab   = (const float*)d_in[7];
    const float* w1     = (const float*)d_in[8];
    const float* b1     = (const float*)d_in[9];
    const float* w2     = (const float*)d_in[10];
    const float* b2     = (const float*)d_in[11];
    float* out = (float*)d_out;

    __half *xnh, *oh, *xn2h, *hh, *qkvh, *wq, *wp, *w1h, *w2h;
    float *x1;
    cudaGetSymbolAddress((void**)&xnh,  g_xnh);
    cudaGetSymbolAddress((void**)&oh,   g_oh);
    cudaGetSymbolAddress((void**)&xn2h, g_xn2h);
    cudaGetSymbolAddress((void**)&hh,   g_hh);
    cudaGetSymbolAddress((void**)&qkvh, g_qkvh);
    cudaGetSymbolAddress((void**)&wq,   g_wq);
    cudaGetSymbolAddress((void**)&wp,   g_wp);
    cudaGetSymbolAddress((void**)&w1h,  g_w1h);
    cudaGetSymbolAddress((void**)&w2h,  g_w2h);
    cudaGetSymbolAddress((void**)&x1,   g_x1);

    cudaFuncSetAttribute(hgemm1<0>, cudaFuncAttributeMaxDynamicSharedMemorySize, HG_SMEM);
    cudaFuncSetAttribute(hgemm1<1>, cudaFuncAttributeMaxDynamicSharedMemorySize, HG_SMEM);
    cudaFuncSetAttribute(hgemm1<2>, cudaFuncAttributeMaxDynamicSharedMemorySize, HG_SMEM);
    cudaFuncSetAttribute(hgemm1<3>, cudaFuncAttributeMaxDynamicSharedMemorySize, HG_SMEM);
    cudaFuncSetAttribute(attn_kernel, cudaFuncAttributeMaxDynamicSharedMemorySize, ATT_SMEM);

    // weight prep (fp16 transpose, pitched)
    wprep_t<<<(CDIM * QKVDIM + 255) / 256, 256>>>(qkv_w,  wq,  CDIM, QKVDIM, APITCH);
    wprep_t<<<(CDIM * CDIM   + 255) / 256, 256>>>(proj_w, wp,  CDIM, CDIM,   APITCH);
    wprep_t<<<(CDIM * NMLP   + 255) / 256, 256>>>(w1,     w1h, CDIM, NMLP,   APITCH);
    wprep_t<<<(NMLP * CDIM   + 255) / 256, 256>>>(w2,     w2h, NMLP, CDIM,   NMLP);

    // 1) LN1(x) -> fp16 (pitched)
    ln_h_kernel<<<NTOK / 8, 256>>>(x, gamma, beta, xnh);
    // 2) qkv = xn @ qkv_w + qkv_b   (fp16 out)
    hgemm1<3><<<dim3(QKVDIM / 128, NTOK / 128), 256, HG_SMEM>>>(
        xnh, wq, qkv_b, nullptr, nullptr, qkvh, NTOK, QKVDIM, CDIM, APITCH, APITCH);
    // 3) windowed attention -> fp16 (pitched)
    attn_kernel<<<BATCH * NWIN, 256, ATT_SMEM>>>(qkvh, btab, oh);
    // 4) x1 = x + o @ proj_w + proj_b
    hgemm1<1><<<dim3(CDIM / 128, NTOK / 128), 256, HG_SMEM>>>(
        oh, wp, proj_b, x, x1, nullptr, NTOK, CDIM, CDIM, APITCH, APITCH);
    // 5) LN2(x1) -> fp16 (pitched)
    ln_h_kernel<<<NTOK / 8, 256>>>(x1, gamma, beta, xn2h);
    // 6) h = gelu(xn2 @ w1 + b1) -> fp16 (2KB rows)
    hgemm1<0><<<dim3(NMLP / 128, NTOK / 128), 256, HG_SMEM>>>(
        xn2h, w1h, b1, nullptr, nullptr, hh, NTOK, NMLP, CDIM, APITCH, APITCH);
    // 7) out = x1 + h @ w2 + b2
    hgemm1<1><<<dim3(CDIM / 128, NTOK / 128), 256, HG_SMEM>>>(
        hh, w2h, b2, x1, out, nullptr, NTOK, CDIM, NMLP, NMLP, NMLP);
}

// round 13
// speedup vs baseline: 2.0346x; 1.0430x over previous
#include <cuda_runtime.h>
#include <cuda_fp16.h>
#include <cstdint>
#include <cstddef>

// ---------------- static problem config ----------------
#define IMG    56
#define WIN    7
#define SHIFTS 3
#define CDIM   256
#define NHEAD  8
#define DHEAD  32
#define SWIN   49
#define NWIN   64
#define NMLP   1024
#define BATCH  32
#define NTOK   (BATCH*IMG*IMG)           // 100352
#define QSCALE 0.17677669529663689f
#define APITCH 320                       // 640B rows: avoids bit-9 L2-slice collision
#define QKVDIM (3*CDIM)                  // 768

// ---------------- scratch (device globals) ----------------
__device__ __half g_xnh [(size_t)NTOK * APITCH];   // LN1 out fp16 (pitched)
__device__ __half g_oh  [(size_t)NTOK * APITCH];   // attn out fp16 (pitched)
__device__ __half g_xn2h[(size_t)NTOK * APITCH];   // LN2 out fp16 (pitched)
__device__ __half g_hh  [(size_t)NTOK * NMLP];     // gelu out fp16 (2KB rows, safe)
__device__ __half g_qkvh[(size_t)NTOK * QKVDIM];   // qkv fp16
__device__ float  g_x1  [(size_t)NTOK * CDIM];     // x + attn
__device__ __half g_wq  [(size_t)QKVDIM * APITCH]; // weights [N,K] fp16 (pitched)
__device__ __half g_wp  [(size_t)CDIM * APITCH];
__device__ __half g_w1h [(size_t)NMLP * APITCH];
__device__ __half g_w2h [(size_t)CDIM * NMLP];     // 2KB rows, safe

// ---------------- helpers ----------------
__device__ __forceinline__ float gelu_exact(float v) {
    return 0.5f * v * (1.0f + erff(v * 0.70710678118654752f));
}
__device__ __forceinline__ uint32_t smem_u32(const void* p) {
    uint32_t a;
    asm("{ .reg .u64 t; cvta.to.shared.u64 t, %1; cvt.u32.u64 %0, t; }"
        : "=r"(a) : "l"(p));
    return a;
}
__device__ __forceinline__ void ldsm4(uint32_t* r, uint32_t addr) {
    asm volatile("ldmatrix.sync.aligned.m8n8.x4.shared.b16 {%0,%1,%2,%3}, [%4];"
        : "=r"(r[0]), "=r"(r[1]), "=r"(r[2]), "=r"(r[3]) : "r"(addr));
}
__device__ __forceinline__ void mma16816(float* c, const uint32_t* a,
                                         uint32_t b0, uint32_t b1) {
    asm volatile("mma.sync.aligned.m16n8k16.row.col.f32.f16.f16.f32 "
        "{%0,%1,%2,%3}, {%4,%5,%6,%7}, {%8,%9}, {%0,%1,%2,%3};"
        : "+f"(c[0]), "+f"(c[1]), "+f"(c[2]), "+f"(c[3])
        : "r"(a[0]), "r"(a[1]), "r"(a[2]), "r"(a[3]), "r"(b0), "r"(b1));
}
__device__ __forceinline__ void cpa16(uint32_t s, const void* g) {
    asm volatile("cp.async.cg.shared.global [%0], [%1], 16;" :: "r"(s), "l"(g));
}
#define CP_COMMIT() asm volatile("cp.async.commit_group;" ::: "memory")
#define CP_WAIT1()  asm volatile("cp.async.wait_group 1;" ::: "memory")
#define CP_WAIT0()  asm volatile("cp.async.wait_group 0;" ::: "memory")

// ---------------- merged weight prep: 4 transposes in one launch ----------------
#define WS0 (CDIM*QKVDIM)                 // 196608
#define WS1 (WS0 + CDIM*CDIM)             // 262144
#define WS2 (WS1 + CDIM*NMLP)             // 524288
#define WS3 (WS2 + NMLP*CDIM)             // 786432
__global__ void wprep_all(const float* __restrict__ qkv_w, const float* __restrict__ proj_w,
                          const float* __restrict__ w1,    const float* __restrict__ w2,
                          __half* __restrict__ wq, __half* __restrict__ wp,
                          __half* __restrict__ w1h, __half* __restrict__ w2h)
{
    int gid = blockIdx.x * 256 + threadIdx.x;
    if (gid < WS0) {
        int idx = gid, N = QKVDIM;
        int k = idx / N, n = idx - k * N;
        wq[(size_t)n * APITCH + k] = __float2half_rn(qkv_w[idx]);
    } else if (gid < WS1) {
        int idx = gid - WS0, N = CDIM;
        int k = idx / N, n = idx - k * N;
        wp[(size_t)n * APITCH + k] = __float2half_rn(proj_w[idx]);
    } else if (gid < WS2) {
        int idx = gid - WS1, N = NMLP;
        int k = idx / N, n = idx - k * N;
        w1h[(size_t)n * APITCH + k] = __float2half_rn(w1[idx]);
    } else if (gid < WS3) {
        int idx = gid - WS2, N = CDIM;
        int k = idx / N, n = idx - k * N;
        w2h[(size_t)n * NMLP + k] = __float2half_rn(w2[idx]);
    }
}

// ---------------- LayerNorm -> fp16 (pitched): one warp per token ----------------
__global__ __launch_bounds__(256) void ln_h_kernel(
    const float* __restrict__ x,
    const float* __restrict__ gamma,
    const float* __restrict__ beta,
    __half* __restrict__ outh)   // [NTOK, APITCH] fp16
{
    int lane = threadIdx.x & 31;
    int warp = threadIdx.x >> 5;
    int tok  = blockIdx.x * 8 + warp;

    const float4* px = (const float4*)(x + (size_t)tok * CDIM);
    float4 v0 = px[lane];
    float4 v1 = px[lane + 32];

    float s  = v0.x + v0.y + v0.z + v0.w + v1.x + v1.y + v1.z + v1.w;
    float ss = v0.x*v0.x + v0.y*v0.y + v0.z*v0.z + v0.w*v0.w
             + v1.x*v1.x + v1.y*v1.y + v1.z*v1.z + v1.w*v1.w;
    #pragma unroll
    for (int o = 16; o; o >>= 1) {
        s  += __shfl_xor_sync(0xffffffffu, s,  o);
        ss += __shfl_xor_sync(0xffffffffu, ss, o);
    }
    float mu  = s * (1.0f / 256.0f);
    float var = ss * (1.0f / 256.0f) - mu * mu;
    float rs  = rsqrtf(var + 1e-5f);

    const float4* pg = (const float4*)gamma;
    const float4* pb = (const float4*)beta;
    float4 g0 = pg[lane], g1 = pg[lane + 32];
    float4 b0 = pb[lane], b1 = pb[lane + 32];

    __half2 o0, o1, o2, o3;
    o0.x = __float2half_rn((v0.x - mu) * rs * g0.x + b0.x);
    o0.y = __float2half_rn((v0.y - mu) * rs * g0.y + b0.y);
    o1.x = __float2half_rn((v0.z - mu) * rs * g0.z + b0.z);
    o1.y = __float2half_rn((v0.w - mu) * rs * g0.w + b0.w);
    o2.x = __float2half_rn((v1.x - mu) * rs * g1.x + b1.x);
    o2.y = __float2half_rn((v1.y - mu) * rs * g1.y + b1.y);
    o3.x = __float2half_rn((v1.z - mu) * rs * g1.z + b1.z);
    o3.y = __float2half_rn((v1.w - mu) * rs * g1.w + b1.w);

    __half* base = outh + (size_t)tok * APITCH;
    *(__half2*)(base + lane * 4)           = o0;
    *(__half2*)(base + lane * 4 + 2)       = o1;
    *(__half2*)(base + 128 + lane * 4)     = o2;
    *(__half2*)(base + 128 + lane * 4 + 2) = o3;
}

// ---------------- HMMA GEMM: 128x128 tile, BK=64, 3-stage ring, 1 sync/chunk ----------------
// EPI 0: outh = fp16(gelu(acc+bias)); EPI 1: outf = res+acc+bias;
// EPI 2: outf = acc+bias;             EPI 3: outh = fp16(acc+bias)
#define HG_SMEM 98304

template<int EPI>
__global__ __launch_bounds__(256, 2) void hgemm1(
    const __half* __restrict__ A,
    const __half* __restrict__ Bw,
    const float* __restrict__ bias,
    const float* __restrict__ res,
    float* __restrict__ outf,
    __half* __restrict__ outh,
    int M, int N, int K, int lda, int ldb)
{
    extern __shared__ char smem[];
    const uint32_t sAb = smem_u32(smem);            // 3 x 16KB
    const uint32_t sBb = sAb + 49152;               // 3 x 16KB

    const int tid  = threadIdx.x;
    const int lane = tid & 31;
    const int wid  = tid >> 5;
    const int wm   = wid >> 1;       // 0..3
    const int wn   = wid & 1;        // 0..1
    const int row0 = blockIdx.y * 128;
    const int col0 = blockIdx.x * 128;
    const int nch  = K / 64;

    float acc[2][8][4];
    #pragma unroll
    for (int a = 0; a < 2; a++)
        #pragma unroll
        for (int b = 0; b < 8; b++)
            #pragma unroll
            for (int c = 0; c < 4; c++) acc[a][b][c] = 0.f;

    auto issue = [&](int g) {
        int slot = g % 3;
        uint32_t sa = sAb + slot * 16384;
        uint32_t sb = sBb + slot * 16384;
        #pragma unroll
        for (int i = 0; i < 4; i++) {
            int id = tid + i * 256;
            int r = id >> 3, kg = id & 7;
            int sg = kg ^ (r & 7);
            uint32_t so = (uint32_t)(r * 128 + sg * 16);
            cpa16(sa + so, A  + (size_t)(row0 + r) * lda + g * 64 + kg * 8);
            cpa16(sb + so, Bw + (size_t)(col0 + r) * ldb + g * 64 + kg * 8);
        }
        CP_COMMIT();
    };

    issue(0);
    issue(1);
    for (int g = 0; g < nch; g++) {
        if (g + 1 < nch) { CP_WAIT1(); }
        else             { CP_WAIT0(); }
        __syncthreads();
        if (g + 2 < nch) issue(g + 2);

        const int slot = g % 3;
        const uint32_t aB = sAb + slot * 16384;
        const uint32_t bB = sBb + slot * 16384;
        #pragma unroll
        for (int kt = 0; kt < 4; kt++) {
            uint32_t a[2][4], b[4][4];
            const int kg = kt * 2 + (lane >> 4);
            #pragma unroll
            for (int mt = 0; mt < 2; mt++) {
                int r  = wm * 32 + mt * 16 + (lane & 15);
                int sg = kg ^ (r & 7);
                ldsm4(a[mt], aB + (uint32_t)(r * 128 + sg * 16));
            }
            #pragma unroll
            for (int nb = 0; nb < 4; nb++) {
                int r  = wn * 64 + nb * 16 + (lane & 15);
                int sg = kg ^ (r & 7);
                ldsm4(b[nb], bB + (uint32_t)(r * 128 + sg * 16));
            }
            #pragma unroll
            for (int mt = 0; mt < 2; mt++)
                #pragma unroll
                for (int nb = 0; nb < 4; nb++) {
                    mma16816(acc[mt][2 * nb],     a[mt], b[nb][0], b[nb][2]);
                    mma16816(acc[mt][2 * nb + 1], a[mt], b[nb][1], b[nb][3]);
                }
        }
    }
    __syncthreads();

    // epilogue
    const int g4 = lane >> 2, q = lane & 3;
    #pragma unroll
    for (int mt = 0; mt < 2; mt++) {
        #pragma unroll
        for (int half = 0; half < 2; half++) {
            int row = row0 + wm * 32 + mt * 16 + g4 + half * 8;
            #pragma unroll
            for (int nt = 0; nt < 8; nt++) {
                int col = col0 + wn * 64 + nt * 8 + q * 2;
                float v0 = acc[mt][nt][half * 2 + 0] + bias[col];
                float v1 = acc[mt][nt][half * 2 + 1] + bias[col + 1];
                if (EPI == 2) {
                    *(float2*)(outf + (size_t)row * N + col) = make_float2(v0, v1);
                } else if (EPI == 1) {
                    const float2 rv = *(const float2*)(res + (size_t)row * N + col);
                    *(float2*)(outf + (size_t)row * N + col) =
                        make_float2(v0 + rv.x, v1 + rv.y);
                } else if (EPI == 0) {
                    __half2 hp;
                    hp.x = __float2half_rn(gelu_exact(v0));
                    hp.y = __float2half_rn(gelu_exact(v1));
                    *(__half2*)(outh + (size_t)row * N + col) = hp;
                } else {
                    __half2 hp;
                    hp.x = __float2half_rn(v0);
                    hp.y = __float2half_rn(v1);
                    *(__half2*)(outh + (size_t)row * N + col) = hp;
                }
            }
        }
    }
}

// ---------------- attention: one CTA per window, one warp per head, fp16 staging ----------------
// smem: k fp16 [8][49][36] (28224B) + v half2 t-pairs [8][25][32] (25600B) + ints (392B)
#define KPADH 36
#define NVP   25
#define ATT_SMEM (NHEAD*SWIN*KPADH*2 + NHEAD*NVP*32*4 + 2*SWIN*4)

__global__ __launch_bounds__(256, 4) void attn_kernel(
    const __half* __restrict__ qkv,   // [NTOK, 768] fp16 (q|k|v)
    const float* __restrict__ btab,   // [169, 8]
    __half* __restrict__ o_h)         // [NTOK, APITCH] fp16
{
    extern __shared__ char smc[];
    __half*  kwh = (__half*)smc;                                   // 28224 B
    __half2* vw2 = (__half2*)(smc + NHEAD * SWIN * KPADH * 2);     // 25600 B
    int* tsrc  = (int*)(smc + NHEAD * SWIN * KPADH * 2 + NHEAD * NVP * 32 * 4);
    int* regid = tsrc + SWIN;

    const int tid  = threadIdx.x;
    const int lane = tid & 31;
    const int h    = tid >> 5;

    const int win = blockIdx.x;
    const int b   = win >> 6;
    const int wq  = win & 63;
    const int wy  = wq >> 3;
    const int wx  = wq & 7;

    if (tid < SWIN) {
        int i = tid / 7, j = tid - i * 7;
        int y  = wy * 7 + i;
        int xx = wx * 7 + j;
        int y0 = y  + SHIFTS; if (y0 >= IMG) y0 -= IMG;
        int x0 = xx + SHIFTS; if (x0 >= IMG) x0 -= IMG;
        tsrc[tid] = b * (IMG * IMG) + y0 * IMG + x0;
        int rc = (y <= 48) ? 0 : ((y <= 52) ? 1 : 2);
        regid[tid] = (xx <= 48) ? rc * 3 : ((xx >= 53) ? rc * 3 + 2 : 0);
    }
    __syncthreads();

    // stage this head's k (fp16) and v (half2 t-pairs)
    __half*  kw = kwh + h * (SWIN * KPADH);
    __half2* vw = vw2 + h * (NVP * 32);
    {
        const int hc = h * 32 + lane;
        for (int s = 0; s < SWIN; s++)
            kw[s * KPADH + lane] = qkv[(size_t)tsrc[s] * QKVDIM + CDIM + hc];
        #pragma unroll
        for (int t2 = 0; t2 < NVP; t2++) {
            __half va = qkv[(size_t)tsrc[2 * t2] * QKVDIM + 2 * CDIM + hc];
            __half vb = (2 * t2 + 1 < SWIN)
                ? qkv[(size_t)tsrc[2 * t2 + 1] * QKVDIM + 2 * CDIM + hc]
                : __float2half_rn(0.f);
            vw[t2 * 32 + lane] = __halves2half2(va, vb);
        }
    }
    __syncwarp();

    const int t1  = lane;
    const int t2  = lane + 32;
    const bool v2 = (t2 < SWIN);
    const int t2c = v2 ? t2 : 48;
    const int it1 = t1 / 7,  jt1 = t1 - it1 * 7;
    const int it2 = t2c / 7, jt2 = t2c - it2 * 7;
    const int r1  = regid[t1];
    const int r2  = regid[t2c];

    const uint2* k1p = (const uint2*)(kw + t1  * KPADH);
    const uint2* k2p = (const uint2*)(kw + t2c * KPADH);

    for (int s = 0; s < SWIN; s++) {
        // q row packed as half2: lane<16 holds q[2*lane], q[2*lane+1]
        const size_t qbase = (size_t)tsrc[s] * QKVDIM + h * 32;
        uint32_t qu = *(const uint32_t*)(qkv + qbase + 2 * (lane & 15));

        float a1 = 0.f, a2 = 0.f;
        #pragma unroll
        for (int j = 0; j < 8; j++) {
            uint2 ku1 = k1p[j];
            uint2 ku2 = k2p[j];
            uint32_t qa = __shfl_sync(0xffffffffu, qu, 2 * j);
            uint32_t qb = __shfl_sync(0xffffffffu, qu, 2 * j + 1);
            float2 qa2 = __half22float2(*(__half2*)&qa);
            float2 qb2 = __half22float2(*(__half2*)&qb);
            float2 xa = __half22float2(*(__half2*)&ku1.x);
            float2 xb = __half22float2(*(__half2*)&ku1.y);
            float2 ya = __half22float2(*(__half2*)&ku2.x);
            float2 yb = __half22float2(*(__half2*)&ku2.y);
            a1 = fmaf(qa2.x, xa.x, a1); a1 = fmaf(qa2.y, xa.y, a1);
            a1 = fmaf(qb2.x, xb.x, a1); a1 = fmaf(qb2.y, xb.y, a1);
            a2 = fmaf(qa2.x, ya.x, a2); a2 = fmaf(qa2.y, ya.y, a2);
            a2 = fmaf(qb2.x, yb.x, a2); a2 = fmaf(qb2.y, yb.y, a2);
        }
        a1 *= QSCALE;
        a2 *= QSCALE;

        int i1 = s / 7, j1 = s - i1 * 7;
        int rs = regid[s];
        {
            int ridx = (i1 - it1 + 6) * 13 + (j1 - jt1 + 6);
            a1 += btab[ridx * NHEAD + h];
            if (rs != r1) a1 -= 100.0f;
        }
        if (v2) {
            int ridx = (i1 - it2 + 6) * 13 + (j1 - jt2 + 6);
            a2 += btab[ridx * NHEAD + h];
            if (rs != r2) a2 -= 100.0f;
        } else {
            a2 = -1e30f;
        }

        float m = fmaxf(a1, a2);
        #pragma unroll
        for (int o = 16; o; o >>= 1) m = fmaxf(m, __shfl_xor_sync(0xffffffffu, m, o));
        float e1 = __expf(a1 - m);
        float e2 = v2 ? __expf(a2 - m) : 0.0f;
        float sum = e1 + e2;
        #pragma unroll
        for (int o = 16; o; o >>= 1) sum += __shfl_xor_sync(0xffffffffu, sum, o);
        float inv = 1.0f / sum;
        float p1 = e1 * inv;     // att[s][lane]       (lanes 17..31 of p2 are exactly 0)
        float p2 = e2 * inv;     // att[s][lane+32]

        // pack adjacent-t probability pairs into half2 (even lanes hold pair (2i, 2i+1))
        float p1n = __shfl_down_sync(0xffffffffu, p1, 1);
        float p2n = __shfl_down_sync(0xffffffffu, p2, 1);
        __half2 pp1 = __floats2half2_rn(p1, p1n);
        __half2 pp2 = __floats2half2_rn(p2, p2n);
        uint32_t pv1 = *(uint32_t*)&pp1;
        uint32_t pv2 = *(uint32_t*)&pp2;

        float oa = 0.f;
        #pragma unroll
        for (int i = 0; i < 16; i++) {
            uint32_t pu = __shfl_sync(0xffffffffu, pv1, 2 * i);
            float2 pf = __half22float2(*(__half2*)&pu);
            float2 vv = __half22float2(vw[i * 32 + lane]);
            oa = fmaf(pf.x, vv.x, oa);
            oa = fmaf(pf.y, vv.y, oa);
        }
        #pragma unroll
        for (int i = 16; i < NVP; i++) {
            uint32_t pu = __shfl_sync(0xffffffffu, pv2, 2 * (i - 16));
            float2 pf = __half22float2(*(__half2*)&pu);
            float2 vv = __half22float2(vw[i * 32 + lane]);   // pair slot t=49 is zeroed
            oa = fmaf(pf.x, vv.x, oa);
            oa = fmaf(pf.y, vv.y, oa);
        }
        o_h[(size_t)tsrc[s] * APITCH + h * 32 + lane] = __float2half_rn(oa);
    }
}

// ---------------- launch ----------------
extern "C" void kernel_launch(void* const* d_in, const int* in_sizes, int n_in,
                              void* d_out, int out_size)
{
    const float* x      = (const float*)d_in[0];
    const float* gamma  = (const float*)d_in[1];
    const float* beta   = (const float*)d_in[2];
    const float* qkv_w  = (const float*)d_in[3];
    const float* qkv_b  = (const float*)d_in[4];
    const float* proj_w = (const float*)d_in[5];
    const float* proj_b = (const float*)d_in[6];
    const float* btab   = (const float*)d_in[7];
    const float* w1     = (const float*)d_in[8];
    const float* b1     = (const float*)d_in[9];
    const float* w2     = (const float*)d_in[10];
    const float* b2     = (const float*)d_in[11];
    float* out = (float*)d_out;

    __half *xnh, *oh, *xn2h, *hh, *qkvh, *wq, *wp, *w1h, *w2h;
    float *x1;
    cudaGetSymbolAddress((void**)&xnh,  g_xnh);
    cudaGetSymbolAddress((void**)&oh,   g_oh);
    cudaGetSymbolAddress((void**)&xn2h, g_xn2h);
    cudaGetSymbolAddress((void**)&hh,   g_hh);
    cudaGetSymbolAddress((void**)&qkvh, g_qkvh);
    cudaGetSymbolAddress((void**)&wq,   g_wq);
    cudaGetSymbolAddress((void**)&wp,   g_wp);
    cudaGetSymbolAddress((void**)&w1h,  g_w1h);
    cudaGetSymbolAddress((void**)&w2h,  g_w2h);
    cudaGetSymbolAddress((void**)&x1,   g_x1);

    cudaFuncSetAttribute(hgemm1<0>, cudaFuncAttributeMaxDynamicSharedMemorySize, HG_SMEM);
    cudaFuncSetAttribute(hgemm1<1>, cudaFuncAttributeMaxDynamicSharedMemorySize, HG_SMEM);
    cudaFuncSetAttribute(hgemm1<2>, cudaFuncAttributeMaxDynamicSharedMemorySize, HG_SMEM);
    cudaFuncSetAttribute(hgemm1<3>, cudaFuncAttributeMaxDynamicSharedMemorySize, HG_SMEM);
    cudaFuncSetAttribute(attn_kernel, cudaFuncAttributeMaxDynamicSharedMemorySize, ATT_SMEM);

    // weight prep (fp16 transpose, pitched) — single launch
    wprep_all<<<WS3 / 256, 256>>>(qkv_w, proj_w, w1, w2, wq, wp, w1h, w2h);

    // 1) LN1(x) -> fp16 (pitched)
    ln_h_kernel<<<NTOK / 8, 256>>>(x, gamma, beta, xnh);
    // 2) qkv = xn @ qkv_w + qkv_b   (fp16 out)
    hgemm1<3><<<dim3(QKVDIM / 128, NTOK / 128), 256, HG_SMEM>>>(
        xnh, wq, qkv_b, nullptr, nullptr, qkvh, NTOK, QKVDIM, CDIM, APITCH, APITCH);
    // 3) windowed attention -> fp16 (pitched)
    attn_kernel<<<BATCH * NWIN, 256, ATT_SMEM>>>(qkvh, btab, oh);
    // 4) x1 = x + o @ proj_w + proj_b
    hgemm1<1><<<dim3(CDIM / 128, NTOK / 128), 256, HG_SMEM>>>(
        oh, wp, proj_b, x, x1, nullptr, NTOK, CDIM, CDIM, APITCH, APITCH);
    // 5) LN2(x1) -> fp16 (pitched)
    ln_h_kernel<<<NTOK / 8, 256>>>(x1, gamma, beta, xn2h);
    // 6) h = gelu(xn2 @ w1 + b1) -> fp16 (2KB rows)
    hgemm1<0><<<dim3(NMLP / 128, NTOK / 128), 256, HG_SMEM>>>(
        xn2h, w1h, b1, nullptr, nullptr, hh, NTOK, NMLP, CDIM, APITCH, APITCH);
    // 7) out = x1 + h @ w2 + b2
    hgemm1<1><<<dim3(CDIM / 128, NTOK / 128), 256, HG_SMEM>>>(
        hh, w2h, b2, x1, out, nullptr, NTOK, CDIM, NMLP, NMLP, NMLP);
}

// round 15
// speedup vs baseline: 2.7051x; 1.3295x over previous
#include <cuda_runtime.h>
#include <cuda_fp16.h>
#include <cstdint>
#include <cstddef>

// ---------------- static problem config ----------------
#define IMG    56
#define WIN    7
#define SHIFTS 3
#define CDIM   256
#define NHEAD  8
#define DHEAD  32
#define SWIN   49
#define NWIN   64
#define NMLP   1024
#define BATCH  32
#define NTOK   (BATCH*IMG*IMG)           // 100352
#define QSCALE 0.17677669529663689f
#define APITCH 320                       // 640B rows: avoids bit-9 L2-slice collision
#define QKVDIM (3*CDIM)                  // 768

// ---------------- scratch (device globals) ----------------
__device__ __half g_xnh [(size_t)NTOK * APITCH];   // LN1 out fp16 (pitched)
__device__ __half g_oh  [(size_t)NTOK * APITCH];   // attn out fp16 (pitched)
__device__ __half g_xn2h[(size_t)NTOK * APITCH];   // LN2 out fp16 (pitched)
__device__ __half g_hh  [(size_t)NTOK * NMLP];     // gelu out fp16 (2KB rows, safe)
__device__ __half g_qkvh[(size_t)NTOK * QKVDIM];   // qkv fp16
__device__ float  g_x1  [(size_t)NTOK * CDIM];     // x + attn
__device__ __half g_wq  [(size_t)QKVDIM * APITCH]; // weights [N,K] fp16 (pitched)
__device__ __half g_wp  [(size_t)CDIM * APITCH];
__device__ __half g_w1h [(size_t)NMLP * APITCH];
__device__ __half g_w2h [(size_t)CDIM * NMLP];     // 2KB rows, safe

// ---------------- helpers ----------------
__device__ __forceinline__ float gelu_exact(float v) {
    return 0.5f * v * (1.0f + erff(v * 0.70710678118654752f));
}
__device__ __forceinline__ uint32_t smem_u32(const void* p) {
    uint32_t a;
    asm("{ .reg .u64 t; cvta.to.shared.u64 t, %1; cvt.u32.u64 %0, t; }"
        : "=r"(a) : "l"(p));
    return a;
}
__device__ __forceinline__ void ldsm4(uint32_t* r, uint32_t addr) {
    asm volatile("ldmatrix.sync.aligned.m8n8.x4.shared.b16 {%0,%1,%2,%3}, [%4];"
        : "=r"(r[0]), "=r"(r[1]), "=r"(r[2]), "=r"(r[3]) : "r"(addr));
}
__device__ __forceinline__ void mma16816(float* c, const uint32_t* a,
                                         uint32_t b0, uint32_t b1) {
    asm volatile("mma.sync.aligned.m16n8k16.row.col.f32.f16.f16.f32 "
        "{%0,%1,%2,%3}, {%4,%5,%6,%7}, {%8,%9}, {%0,%1,%2,%3};"
        : "+f"(c[0]), "+f"(c[1]), "+f"(c[2]), "+f"(c[3])
        : "r"(a[0]), "r"(a[1]), "r"(a[2]), "r"(a[3]), "r"(b0), "r"(b1));
}
__device__ __forceinline__ void cpa16(uint32_t s, const void* g) {
    asm volatile("cp.async.cg.shared.global [%0], [%1], 16;" :: "r"(s), "l"(g));
}
#define CP_COMMIT() asm volatile("cp.async.commit_group;" ::: "memory")
#define CP_WAIT1()  asm volatile("cp.async.wait_group 1;" ::: "memory")
#define CP_WAIT0()  asm volatile("cp.async.wait_group 0;" ::: "memory")

// ---------------- merged weight prep: 4 transposes in one launch ----------------
#define WS0 (CDIM*QKVDIM)                 // 196608
#define WS1 (WS0 + CDIM*CDIM)             // 262144
#define WS2 (WS1 + CDIM*NMLP)             // 524288
#define WS3 (WS2 + NMLP*CDIM)             // 786432
__global__ void wprep_all(const float* __restrict__ qkv_w, const float* __restrict__ proj_w,
                          const float* __restrict__ w1,    const float* __restrict__ w2,
                          __half* __restrict__ wq, __half* __restrict__ wp,
                          __half* __restrict__ w1h, __half* __restrict__ w2h)
{
    int gid = blockIdx.x * 256 + threadIdx.x;
    if (gid < WS0) {
        int idx = gid, N = QKVDIM;
        int k = idx / N, n = idx - k * N;
        wq[(size_t)n * APITCH + k] = __float2half_rn(qkv_w[idx]);
    } else if (gid < WS1) {
        int idx = gid - WS0, N = CDIM;
        int k = idx / N, n = idx - k * N;
        wp[(size_t)n * APITCH + k] = __float2half_rn(proj_w[idx]);
    } else if (gid < WS2) {
        int idx = gid - WS1, N = NMLP;
        int k = idx / N, n = idx - k * N;
        w1h[(size_t)n * APITCH + k] = __float2half_rn(w1[idx]);
    } else if (gid < WS3) {
        int idx = gid - WS2, N = CDIM;
        int k = idx / N, n = idx - k * N;
        w2h[(size_t)n * NMLP + k] = __float2half_rn(w2[idx]);
    }
}

// ---------------- LayerNorm -> fp16 (pitched): one warp per token ----------------
__global__ __launch_bounds__(256) void ln_h_kernel(
    const float* __restrict__ x,
    const float* __restrict__ gamma,
    const float* __restrict__ beta,
    __half* __restrict__ outh)   // [NTOK, APITCH] fp16
{
    int lane = threadIdx.x & 31;
    int warp = threadIdx.x >> 5;
    int tok  = blockIdx.x * 8 + warp;

    const float4* px = (const float4*)(x + (size_t)tok * CDIM);
    float4 v0 = px[lane];
    float4 v1 = px[lane + 32];

    float s  = v0.x + v0.y + v0.z + v0.w + v1.x + v1.y + v1.z + v1.w;
    float ss = v0.x*v0.x + v0.y*v0.y + v0.z*v0.z + v0.w*v0.w
             + v1.x*v1.x + v1.y*v1.y + v1.z*v1.z + v1.w*v1.w;
    #pragma unroll
    for (int o = 16; o; o >>= 1) {
        s  += __shfl_xor_sync(0xffffffffu, s,  o);
        ss += __shfl_xor_sync(0xffffffffu, ss, o);
    }
    float mu  = s * (1.0f / 256.0f);
    float var = ss * (1.0f / 256.0f) - mu * mu;
    float rs  = rsqrtf(var + 1e-5f);

    const float4* pg = (const float4*)gamma;
    const float4* pb = (const float4*)beta;
    float4 g0 = pg[lane], g1 = pg[lane + 32];
    float4 b0 = pb[lane], b1 = pb[lane + 32];

    __half2 o0, o1, o2, o3;
    o0.x = __float2half_rn((v0.x - mu) * rs * g0.x + b0.x);
    o0.y = __float2half_rn((v0.y - mu) * rs * g0.y + b0.y);
    o1.x = __float2half_rn((v0.z - mu) * rs * g0.z + b0.z);
    o1.y = __float2half_rn((v0.w - mu) * rs * g0.w + b0.w);
    o2.x = __float2half_rn((v1.x - mu) * rs * g1.x + b1.x);
    o2.y = __float2half_rn((v1.y - mu) * rs * g1.y + b1.y);
    o3.x = __float2half_rn((v1.z - mu) * rs * g1.z + b1.z);
    o3.y = __float2half_rn((v1.w - mu) * rs * g1.w + b1.w);

    __half* base = outh + (size_t)tok * APITCH;
    *(__half2*)(base + lane * 4)           = o0;
    *(__half2*)(base + lane * 4 + 2)       = o1;
    *(__half2*)(base + 128 + lane * 4)     = o2;
    *(__half2*)(base + 128 + lane * 4 + 2) = o3;
}

// ---------------- HMMA GEMM: 128x128 tile, BK=64, 3-stage ring, 1 sync/chunk ----------------
// EPI 0: outh = fp16(gelu(acc+bias)); EPI 1: outf = res+acc+bias;
// EPI 2: outf = acc+bias;             EPI 3: outh = fp16(acc+bias)
#define HG_SMEM 98304

template<int EPI>
__global__ __launch_bounds__(256, 2) void hgemm1(
    const __half* __restrict__ A,
    const __half* __restrict__ Bw,
    const float* __restrict__ bias,
    const float* __restrict__ res,
    float* __restrict__ outf,
    __half* __restrict__ outh,
    int M, int N, int K, int lda, int ldb)
{
    extern __shared__ char smem[];
    const uint32_t sAb = smem_u32(smem);            // 3 x 16KB
    const uint32_t sBb = sAb + 49152;               // 3 x 16KB

    const int tid  = threadIdx.x;
    const int lane = tid & 31;
    const int wid  = tid >> 5;
    const int wm   = wid >> 1;       // 0..3
    const int wn   = wid & 1;        // 0..1
    const int row0 = blockIdx.y * 128;
    const int col0 = blockIdx.x * 128;
    const int nch  = K / 64;

    float acc[2][8][4];
    #pragma unroll
    for (int a = 0; a < 2; a++)
        #pragma unroll
        for (int b = 0; b < 8; b++)
            #pragma unroll
            for (int c = 0; c < 4; c++) acc[a][b][c] = 0.f;

    auto issue = [&](int g) {
        int slot = g % 3;
        uint32_t sa = sAb + slot * 16384;
        uint32_t sb = sBb + slot * 16384;
        #pragma unroll
        for (int i = 0; i < 4; i++) {
            int id = tid + i * 256;
            int r = id >> 3, kg = id & 7;
            int sg = kg ^ (r & 7);
            uint32_t so = (uint32_t)(r * 128 + sg * 16);
            cpa16(sa + so, A  + (size_t)(row0 + r) * lda + g * 64 + kg * 8);
            cpa16(sb + so, Bw + (size_t)(col0 + r) * ldb + g * 64 + kg * 8);
        }
        CP_COMMIT();
    };

    issue(0);
    issue(1);
    for (int g = 0; g < nch; g++) {
        if (g + 1 < nch) { CP_WAIT1(); }
        else             { CP_WAIT0(); }
        __syncthreads();
        if (g + 2 < nch) issue(g + 2);

        const int slot = g % 3;
        const uint32_t aB = sAb + slot * 16384;
        const uint32_t bB = sBb + slot * 16384;
        #pragma unroll
        for (int kt = 0; kt < 4; kt++) {
            uint32_t a[2][4], b[4][4];
            const int kg = kt * 2 + (lane >> 4);
            #pragma unroll
            for (int mt = 0; mt < 2; mt++) {
                int r  = wm * 32 + mt * 16 + (lane & 15);
                int sg = kg ^ (r & 7);
                ldsm4(a[mt], aB + (uint32_t)(r * 128 + sg * 16));
            }
            #pragma unroll
            for (int nb = 0; nb < 4; nb++) {
                int r  = wn * 64 + nb * 16 + (lane & 15);
                int sg = kg ^ (r & 7);
                ldsm4(b[nb], bB + (uint32_t)(r * 128 + sg * 16));
            }
            #pragma unroll
            for (int mt = 0; mt < 2; mt++)
                #pragma unroll
                for (int nb = 0; nb < 4; nb++) {
                    mma16816(acc[mt][2 * nb],     a[mt], b[nb][0], b[nb][2]);
                    mma16816(acc[mt][2 * nb + 1], a[mt], b[nb][1], b[nb][3]);
                }
        }
    }
    __syncthreads();

    // epilogue
    const int g4 = lane >> 2, q = lane & 3;
    #pragma unroll
    for (int mt = 0; mt < 2; mt++) {
        #pragma unroll
        for (int half = 0; half < 2; half++) {
            int row = row0 + wm * 32 + mt * 16 + g4 + half * 8;
            #pragma unroll
            for (int nt = 0; nt < 8; nt++) {
                int col = col0 + wn * 64 + nt * 8 + q * 2;
                float v0 = acc[mt][nt][half * 2 + 0] + bias[col];
                float v1 = acc[mt][nt][half * 2 + 1] + bias[col + 1];
                if (EPI == 2) {
                    *(float2*)(outf + (size_t)row * N + col) = make_float2(v0, v1);
                } else if (EPI == 1) {
                    const float2 rv = *(const float2*)(res + (size_t)row * N + col);
                    *(float2*)(outf + (size_t)row * N + col) =
                        make_float2(v0 + rv.x, v1 + rv.y);
                } else if (EPI == 0) {
                    __half2 hp;
                    hp.x = __float2half_rn(gelu_exact(v0));
                    hp.y = __float2half_rn(gelu_exact(v1));
                    *(__half2*)(outh + (size_t)row * N + col) = hp;
                } else {
                    __half2 hp;
                    hp.x = __float2half_rn(v0);
                    hp.y = __float2half_rn(v1);
                    *(__half2*)(outh + (size_t)row * N + col) = hp;
                }
            }
        }
    }
}

// ---------------- MMA attention: CTA = window (1024 thr), warp = (head, m-quarter) ----------------
// S = Q@K^T via m16n8k16 (frags gathered straight from gmem), bias+mask on C-frags,
// register softmax, C->A identity for P, O = P@V with u16-pair V gathers.
__global__ __launch_bounds__(1024, 1) void attn_kernel(
    const __half* __restrict__ qkv,   // [NTOK, 768] fp16 (q|k|v)
    const float* __restrict__ btab,   // [169, 8]
    __half* __restrict__ o_h)         // [NTOK, APITCH] fp16
{
    __shared__ float btab_s[NHEAD * 169];   // [h][169]
    __shared__ int   tsrc_s[SWIN];
    __shared__ int   rc_s[SWIN];            // 13*i + j
    __shared__ int   regid_s[SWIN];

    const int tid  = threadIdx.x;
    const int lane = tid & 31;
    const int w    = tid >> 5;
    const int h    = w >> 2;      // head
    const int mq   = w & 3;       // m-quarter (rows 16*mq..)

    const int win = blockIdx.x;
    const int b   = win >> 6;
    const int wq  = win & 63;
    const int wy  = wq >> 3;
    const int wx  = wq & 7;

    if (tid < SWIN) {
        int i = tid / 7, j = tid - i * 7;
        int y  = wy * 7 + i;
        int xx = wx * 7 + j;
        int y0 = y  + SHIFTS; if (y0 >= IMG) y0 -= IMG;
        int x0 = xx + SHIFTS; if (x0 >= IMG) x0 -= IMG;
        tsrc_s[tid] = b * (IMG * IMG) + y0 * IMG + x0;
        rc_s[tid]   = i * 13 + j;
        int rc = (y <= 48) ? 0 : ((y <= 52) ? 1 : 2);
        regid_s[tid] = (xx <= 48) ? rc * 3 : ((xx >= 53) ? rc * 3 + 2 : 0);
    }
    for (int idx = tid; idx < 169 * NHEAD; idx += 1024)
        btab_s[(idx & 7) * 169 + (idx >> 3)] = btab[idx];
    __syncthreads();

    // rows owned by this lane
    const int dq  = 2 * (lane & 3);
    const int r1  = 16 * mq + (lane >> 2);
    const int r2  = r1 + 8;
    const int r1c = (r1 < SWIN) ? r1 : 48;
    const int r2c = (r2 < SWIN) ? r2 : 48;
    const int ts1 = tsrc_s[r1c];
    const int ts2 = tsrc_s[r2c];
    const int rc1 = rc_s[r1c], rg1 = regid_s[r1c];
    const int rc2 = rc_s[r2c], rg2 = regid_s[r2c];

    // Q A-fragments (2 k-tiles of d)
    uint32_t Aq[2][4];
    {
        const __half* q1 = qkv + (size_t)ts1 * QKVDIM + h * 32;
        const __half* q2 = qkv + (size_t)ts2 * QKVDIM + h * 32;
        #pragma unroll
        for (int kk = 0; kk < 2; kk++) {
            int off = 16 * kk;
            Aq[kk][0] = *(const uint32_t*)(q1 + off + dq);
            Aq[kk][1] = *(const uint32_t*)(q2 + off + dq);
            Aq[kk][2] = *(const uint32_t*)(q1 + off + dq + 8);
            Aq[kk][3] = *(const uint32_t*)(q2 + off + dq + 8);
        }
    }

    // S = Q @ K^T  (7 n-tiles of 8 tokens)
    float S[7][4];
    #pragma unroll
    for (int nt = 0; nt < 7; nt++)
        #pragma unroll
        for (int e = 0; e < 4; e++) S[nt][e] = 0.f;

    #pragma unroll
    for (int nt = 0; nt < 7; nt++) {
        int t  = 8 * nt + (lane >> 2);
        int tc = (t < SWIN) ? t : 48;
        const __half* kb = qkv + (size_t)tsrc_s[tc] * QKVDIM + CDIM + h * 32;
        uint32_t b00 = *(const uint32_t*)(kb + dq);
        uint32_t b01 = *(const uint32_t*)(kb + dq + 8);
        uint32_t b10 = *(const uint32_t*)(kb + 16 + dq);
        uint32_t b11 = *(const uint32_t*)(kb + 24 + dq);
        mma16816(S[nt], Aq[0], b00, b01);
        mma16816(S[nt], Aq[1], b10, b11);
    }

    // scale + bias + mask
    #pragma unroll
    for (int nt = 0; nt < 7; nt++) {
        int c0  = 8 * nt + dq;
        int c1  = c0 + 1;
        int c0c = (c0 < SWIN) ? c0 : 48;
        int c1c = (c1 < SWIN) ? c1 : 48;
        int cc0 = rc_s[c0c], rgc0 = regid_s[c0c];
        int cc1 = rc_s[c1c], rgc1 = regid_s[c1c];
        const float* bh = btab_s + h * 169 + 84;
        float s0 = S[nt][0] * QSCALE + bh[rc1 - cc0] + ((rg1 != rgc0) ? -100.f : 0.f);
        float s1 = S[nt][1] * QSCALE + bh[rc1 - cc1] + ((rg1 != rgc1) ? -100.f : 0.f);
        float s2 = S[nt][2] * QSCALE + bh[rc2 - cc0] + ((rg2 != rgc0) ? -100.f : 0.f);
        float s3 = S[nt][3] * QSCALE + bh[rc2 - cc1] + ((rg2 != rgc1) ? -100.f : 0.f);
        S[nt][0] = (c0 < SWIN) ? s0 : -1e30f;
        S[nt][1] = (c1 < SWIN) ? s1 : -1e30f;
        S[nt][2] = (c0 < SWIN) ? s2 : -1e30f;
        S[nt][3] = (c1 < SWIN) ? s3 : -1e30f;
    }

    // row softmax (rows live across 4-lane groups: shfl_xor 1,2)
    float m1 = -1e30f, m2 = -1e30f;
    #pragma unroll
    for (int nt = 0; nt < 7; nt++) {
        m1 = fmaxf(m1, fmaxf(S[nt][0], S[nt][1]));
        m2 = fmaxf(m2, fmaxf(S[nt][2], S[nt][3]));
    }
    m1 = fmaxf(m1, __shfl_xor_sync(0xffffffffu, m1, 1));
    m1 = fmaxf(m1, __shfl_xor_sync(0xffffffffu, m1, 2));
    m2 = fmaxf(m2, __shfl_xor_sync(0xffffffffu, m2, 1));
    m2 = fmaxf(m2, __shfl_xor_sync(0xffffffffu, m2, 2));

    float sum1 = 0.f, sum2 = 0.f;
    #pragma unroll
    for (int nt = 0; nt < 7; nt++) {
        S[nt][0] = __expf(S[nt][0] - m1); sum1 += S[nt][0];
        S[nt][1] = __expf(S[nt][1] - m1); sum1 += S[nt][1];
        S[nt][2] = __expf(S[nt][2] - m2); sum2 += S[nt][2];
        S[nt][3] = __expf(S[nt][3] - m2); sum2 += S[nt][3];
    }
    sum1 += __shfl_xor_sync(0xffffffffu, sum1, 1);
    sum1 += __shfl_xor_sync(0xffffffffu, sum1, 2);
    sum2 += __shfl_xor_sync(0xffffffffu, sum2, 1);
    sum2 += __shfl_xor_sync(0xffffffffu, sum2, 2);
    const float inv1 = 1.0f / sum1;
    const float inv2 = 1.0f / sum2;

    // P = softmax(S) packed as A-fragments (C->A identity); k-tile 3 upper half = 0
    uint32_t P[4][4];
    #pragma unroll
    for (int kk = 0; kk < 4; kk++) {
        int na = 2 * kk, nb = 2 * kk + 1;
        __half2 p0 = __floats2half2_rn(S[na][0] * inv1, S[na][1] * inv1);
        __half2 p1 = __floats2half2_rn(S[na][2] * inv2, S[na][3] * inv2);
        P[kk][0] = *(uint32_t*)&p0;
        P[kk][1] = *(uint32_t*)&p1;
        if (nb < 7) {
            __half2 p2 = __floats2half2_rn(S[nb][0] * inv1, S[nb][1] * inv1);
            __half2 p3 = __floats2half2_rn(S[nb][2] * inv2, S[nb][3] * inv2);
            P[kk][2] = *(uint32_t*)&p2;
            P[kk][3] = *(uint32_t*)&p3;
        } else {
            P[kk][2] = 0u;
            P[kk][3] = 0u;
        }
    }

    // O = P @ V  (V B-frags gathered as u16 pairs; padded t clamps are multiplied by p=0)
    float O[4][4];
    #pragma unroll
    for (int nt = 0; nt < 4; nt++)
        #pragma unroll
        for (int e = 0; e < 4; e++) O[nt][e] = 0.f;

    #pragma unroll
    for (int kk = 0; kk < 4; kk++) {
        int ta  = 16 * kk + dq;
        int t0  = (ta     < SWIN) ? ta     : 48;
        int t1  = (ta + 1 < SWIN) ? ta + 1 : 48;
        int t2  = (ta + 8 < SWIN) ? ta + 8 : 48;
        int t3  = (ta + 9 < SWIN) ? ta + 9 : 48;
        const unsigned short* v0p = (const unsigned short*)(qkv + (size_t)tsrc_s[t0] * QKVDIM + 2 * CDIM + h * 32);
        const unsigned short* v1p = (const unsigned short*)(qkv + (size_t)tsrc_s[t1] * QKVDIM + 2 * CDIM + h * 32);
        const unsigned short* v2p = (const unsigned short*)(qkv + (size_t)tsrc_s[t2] * QKVDIM + 2 * CDIM + h * 32);
        const unsigned short* v3p = (const unsigned short*)(qkv + (size_t)tsrc_s[t3] * QKVDIM + 2 * CDIM + h * 32);
        #pragma unroll
        for (int nt = 0; nt < 4; nt++) {
            int d = 8 * nt + (lane >> 2);
            uint32_t b0 = (uint32_t)v0p[d] | ((uint32_t)v1p[d] << 16);
            uint32_t b1 = (uint32_t)v2p[d] | ((uint32_t)v3p[d] << 16);
            mma16816(O[nt], P[kk], b0, b1);
        }
    }

    // store (predicated on real rows)
    #pragma unroll
    for (int nt = 0; nt < 4; nt++) {
        int d = 8 * nt + dq;
        if (r1 < SWIN) {
            __half2 ov = __floats2half2_rn(O[nt][0], O[nt][1]);
            *(__half2*)(o_h + (size_t)ts1 * APITCH + h * 32 + d) = ov;
        }
        if (r2 < SWIN) {
            __half2 ov = __floats2half2_rn(O[nt][2], O[nt][3]);
            *(__half2*)(o_h + (size_t)ts2 * APITCH + h * 32 + d) = ov;
        }
    }
}

// ---------------- launch ----------------
extern "C" void kernel_launch(void* const* d_in, const int* in_sizes, int n_in,
                              void* d_out, int out_size)
{
    const float* x      = (const float*)d_in[0];
    const float* gamma  = (const float*)d_in[1];
    const float* beta   = (const float*)d_in[2];
    const float* qkv_w  = (const float*)d_in[3];
    const float* qkv_b  = (const float*)d_in[4];
    const float* proj_w = (const float*)d_in[5];
    const float* proj_b = (const float*)d_in[6];
    const float* btab   = (const float*)d_in[7];
    const float* w1     = (const float*)d_in[8];
    const float* b1     = (const float*)d_in[9];
    const float* w2     = (const float*)d_in[10];
    const float* b2     = (const float*)d_in[11];
    float* out = (float*)d_out;

    __half *xnh, *oh, *xn2h, *hh, *qkvh, *wq, *wp, *w1h, *w2h;
    float *x1;
    cudaGetSymbolAddress((void**)&xnh,  g_xnh);
    cudaGetSymbolAddress((void**)&oh,   g_oh);
    cudaGetSymbolAddress((void**)&xn2h, g_xn2h);
    cudaGetSymbolAddress((void**)&hh,   g_hh);
    cudaGetSymbolAddress((void**)&qkvh, g_qkvh);
    cudaGetSymbolAddress((void**)&wq,   g_wq);
    cudaGetSymbolAddress((void**)&wp,   g_wp);
    cudaGetSymbolAddress((void**)&w1h,  g_w1h);
    cudaGetSymbolAddress((void**)&w2h,  g_w2h);
    cudaGetSymbolAddress((void**)&x1,   g_x1);

    cudaFuncSetAttribute(hgemm1<0>, cudaFuncAttributeMaxDynamicSharedMemorySize, HG_SMEM);
    cudaFuncSetAttribute(hgemm1<1>, cudaFuncAttributeMaxDynamicSharedMemorySize, HG_SMEM);
    cudaFuncSetAttribute(hgemm1<2>, cudaFuncAttributeMaxDynamicSharedMemorySize, HG_SMEM);
    cudaFuncSetAttribute(hgemm1<3>, cudaFuncAttributeMaxDynamicSharedMemorySize, HG_SMEM);

    // weight prep (fp16 transpose, pitched) — single launch
    wprep_all<<<WS3 / 256, 256>>>(qkv_w, proj_w, w1, w2, wq, wp, w1h, w2h);

    // 1) LN1(x) -> fp16 (pitched)
    ln_h_kernel<<<NTOK / 8, 256>>>(x, gamma, beta, xnh);
    // 2) qkv = xn @ qkv_w + qkv_b   (fp16 out)
    hgemm1<3><<<dim3(QKVDIM / 128, NTOK / 128), 256, HG_SMEM>>>(
        xnh, wq, qkv_b, nullptr, nullptr, qkvh, NTOK, QKVDIM, CDIM, APITCH, APITCH);
    // 3) windowed attention (MMA) -> fp16 (pitched)
    attn_kernel<<<BATCH * NWIN, 1024>>>(qkvh, btab, oh);
    // 4) x1 = x + o @ proj_w + proj_b
    hgemm1<1><<<dim3(CDIM / 128, NTOK / 128), 256, HG_SMEM>>>(
        oh, wp, proj_b, x, x1, nullptr, NTOK, CDIM, CDIM, APITCH, APITCH);
    // 5) LN2(x1) -> fp16 (pitched)
    ln_h_kernel<<<NTOK / 8, 256>>>(x1, gamma, beta, xn2h);
    // 6) h = gelu(xn2 @ w1 + b1) -> fp16 (2KB rows)
    hgemm1<0><<<dim3(NMLP / 128, NTOK / 128), 256, HG_SMEM>>>(
        xn2h, w1h, b1, nullptr, nullptr, hh, NTOK, NMLP, CDIM, APITCH, APITCH);
    // 7) out = x1 + h @ w2 + b2
    hgemm1<1><<<dim3(CDIM / 128, NTOK / 128), 256, HG_SMEM>>>(
        hh, w2h, b2, x1, out, nullptr, NTOK, CDIM, NMLP, NMLP, NMLP);
}